// round 1
// baseline (speedup 1.0000x reference)
#include <cuda_runtime.h>
#include <math.h>

#define BB 8
#define CIN 64
#define NP 1024
#define KK 32
#define MM 8
#define CO 64
#define TILES (BB*NP)

// device scratch (no allocations allowed)
__device__ float g_Wp[CIN*MM*CO];        // (c*8+m)*64+o, scaled by bn_g[o]/sqrt(1+eps)
__device__ float g_scores[BB*NP*KK*MM];  // ((b*N+n)*K+k)*8+m
__device__ float g_P[BB*NP*MM*CO];       // ((b*N+n)*8+m)*64+o, scaled
__device__ int   g_ctr[2];

#define FMA2(d,a,b)  asm("fma.rn.f32x2 %0, %1, %2, %0;" : "+l"(d) : "l"(a), "l"(b))
#define PACK2(d,x)   asm("mov.b64 %0, {%1, %1};" : "=l"(d) : "f"(x))
#define UNPACK2(lo,hi,v) asm("mov.b64 {%0, %1}, %2;" : "=f"(lo), "=f"(hi) : "l"(v))

__global__ void reset_kernel() {
    if (threadIdx.x < 2) g_ctr[threadIdx.x] = 0;
}

// W'[c,m,o] = (wb[c,m,o] + wb[c+64,m,o]) * bn_g[o]/sqrt(1+eps)
// wb layout (128,8,64) row-major == g_Wp layout (c*8+m)*64+o, so index-identical.
__global__ void prep_kernel(const float* __restrict__ wb, const float* __restrict__ bng) {
    int i = blockIdx.x*blockDim.x + threadIdx.x;
    if (i < CIN*MM*CO) {
        float sc = bng[i & 63] * rsqrtf(1.f + 1e-5f);
        g_Wp[i] = (wb[i] + wb[i + CIN*MM*CO]) * sc;
    }
}

// per-point score MLP + softmax
__global__ void scores_kernel(const float* __restrict__ pts,
    const float* __restrict__ w1, const float* __restrict__ g1, const float* __restrict__ be1,
    const float* __restrict__ w2, const float* __restrict__ g2, const float* __restrict__ be2,
    const float* __restrict__ w3, const float* __restrict__ g3, const float* __restrict__ be3,
    const float* __restrict__ w4, const float* __restrict__ b4)
{
    __shared__ float sw1[112], sw2[256], sw3[256], sw4[128];
    __shared__ float sc1[16], sb1[16], sc2[16], sb2[16], sc3[16], sb3[16], sb4[8];
    int t = threadIdx.x;
    float inv = rsqrtf(1.f + 1e-5f);
    if (t < 112) sw1[t] = w1[t];
    if (t < 256) { sw2[t] = w2[t]; sw3[t] = w3[t]; }
    if (t < 128) sw4[t] = w4[t];
    if (t < 16)  { sc1[t] = g1[t]*inv; sb1[t] = be1[t];
                   sc2[t] = g2[t]*inv; sb2[t] = be2[t];
                   sc3[t] = g3[t]*inv; sb3[t] = be3[t]; }
    if (t < 8)   sb4[t] = b4[t];
    __syncthreads();

    int p  = blockIdx.x*256 + t;     // 0 .. B*N*K-1
    int k  = p & 31;
    int bn = p >> 5;
    int n  = bn & 1023;
    int b  = bn >> 10;

    float xf[7];
    float d2 = 0.f;
#pragma unroll
    for (int d = 0; d < 3; d++) {
        int base = ((b*3 + d)*NP + n)*KK;
        float x  = pts[base + k];
        float cx = pts[base];        // k = 0 (center)
        xf[d] = cx;
        float df = x - cx;
        xf[3 + d] = df;
        d2 += df*df;
    }
    xf[6] = sqrtf(d2);

    float h1[16];
#pragma unroll
    for (int i = 0; i < 16; i++) {
        float a = 0.f;
#pragma unroll
        for (int j = 0; j < 7; j++) a += sw1[i*7 + j]*xf[j];
        h1[i] = fmaxf(a*sc1[i] + sb1[i], 0.f);
    }
    float h2[16];
#pragma unroll
    for (int i = 0; i < 16; i++) {
        float a = 0.f;
#pragma unroll
        for (int j = 0; j < 16; j++) a += sw2[i*16 + j]*h1[j];
        h2[i] = fmaxf(a*sc2[i] + sb2[i], 0.f);
    }
    float h3[16];
#pragma unroll
    for (int i = 0; i < 16; i++) {
        float a = 0.f;
#pragma unroll
        for (int j = 0; j < 16; j++) a += sw3[i*16 + j]*h2[j];
        h3[i] = fmaxf(a*sc3[i] + sb3[i], 0.f);
    }
    float s[8];
#pragma unroll
    for (int i = 0; i < 8; i++) {
        float a = sb4[i];
#pragma unroll
        for (int j = 0; j < 16; j++) a += sw4[i*16 + j]*h3[j];
        s[i] = a;
    }
    float mx = s[0];
#pragma unroll
    for (int i = 1; i < 8; i++) mx = fmaxf(mx, s[i]);
    float sum = 0.f;
#pragma unroll
    for (int i = 0; i < 8; i++) { s[i] = __expf(s[i] - mx); sum += s[i]; }
    float r = 1.f / sum;
#pragma unroll
    for (int i = 0; i < 8; i++) g_scores[p*8 + i] = s[i]*r;
}

// P[b,n,m,o] = sum_c center_feat[b,c,n] * wb_top[c,m,o] * bn_scale[o]   (persistent)
__global__ void __launch_bounds__(256, 1)
p_kernel(const float* __restrict__ feat, const float* __restrict__ wb,
         const float* __restrict__ bng)
{
    extern __shared__ float swb[];   // 64*512 floats = 128KB, pre-scaled wb_top
    __shared__ float cen[64];
    __shared__ int s_tile;
    int t = threadIdx.x;
    float inv = rsqrtf(1.f + 1e-5f);
    for (int i = t; i < CIN*MM*CO; i += 256) swb[i] = wb[i]*bng[i & 63]*inv;
    for (;;) {
        __syncthreads();
        if (t == 0) s_tile = atomicAdd(&g_ctr[0], 1);
        __syncthreads();
        int tile = s_tile;
        if (tile >= TILES) break;
        int b = tile >> 10, n = tile & 1023;
        if (t < 64) cen[t] = feat[((b*64 + t)*NP + n)*KK];   // k=0
        __syncthreads();
#pragma unroll
        for (int r = 0; r < 2; r++) {
            int mo = t + r*256;
            float a = 0.f;
#pragma unroll 8
            for (int c = 0; c < 64; c++) a += cen[c]*swb[c*512 + mo];
            g_P[tile*512 + mo] = a;
        }
    }
}

// main: per (b,n) tile: Y[m,o,k]=sum_c f[c,k]W'[c,m,o]; out=relu(sum_m s*(Y-P)+bn_b)
__global__ void __launch_bounds__(256, 1)
main_kernel(const float* __restrict__ feat, const float* __restrict__ bnb,
            float* __restrict__ out)
{
    extern __shared__ float smem[];
    float* sW = smem;            // 32768 : W' [c*512 + m*64 + o]
    float* sf = sW + 32768;      // 2048  : f  [c*32 + k]
    float* sS = sf + 2048;       // 256   : scores [m*32 + k]
    float* sP = sS + 256;        // 512   : P [m*64 + o]
    float* sB = sP + 512;        // 64    : bn beta
    __shared__ int s_tile;

    int t  = threadIdx.x;
    int tx = t & 31, ty = t >> 5;

    for (int i = t; i < 8192; i += 256)
        ((float4*)sW)[i] = ((const float4*)g_Wp)[i];
    if (t < 64) sB[t] = bnb[t];

    for (;;) {
        __syncthreads();
        if (t == 0) s_tile = atomicAdd(&g_ctr[1], 1);
        __syncthreads();
        int tile = s_tile;
        if (tile >= TILES) break;
        int b = tile >> 10, n = tile & 1023;

        {
            int i = t;
#pragma unroll
            for (int r = 0; r < 2; r++, i += 256) {
                int c = i >> 3, q = i & 7;
                *(float4*)(sf + c*32 + q*4) =
                    *(const float4*)(feat + ((b*64 + c)*NP + n)*KK + q*4);
            }
            sS[(t & 7)*32 + (t >> 3)] = g_scores[tile*256 + t];
            sP[t]       = g_P[tile*512 + t];
            sP[t + 256] = g_P[tile*512 + t + 256];
        }
        __syncthreads();

        unsigned long long acc[4] = {0ull,0ull,0ull,0ull};
        unsigned long long qcc[4] = {0ull,0ull,0ull,0ull};

#pragma unroll
        for (int m0 = 0; m0 < 8; m0 += 2) {
            unsigned long long pY[2][4] = {{0ull,0ull,0ull,0ull},{0ull,0ull,0ull,0ull}};
#pragma unroll 4
            for (int c = 0; c < 64; c++) {
                float fc = sf[c*32 + tx];
                unsigned long long f2; PACK2(f2, fc);
                const float* wr0 = sW + c*512 + m0*64 + (ty << 3);
                double2 a0 = *(const double2*)wr0;
                double2 b0 = *(const double2*)(wr0 + 4);
                FMA2(pY[0][0], f2, __double_as_longlong(a0.x));
                FMA2(pY[0][1], f2, __double_as_longlong(a0.y));
                FMA2(pY[0][2], f2, __double_as_longlong(b0.x));
                FMA2(pY[0][3], f2, __double_as_longlong(b0.y));
                const float* wr1 = wr0 + 64;
                double2 a1 = *(const double2*)wr1;
                double2 b1 = *(const double2*)(wr1 + 4);
                FMA2(pY[1][0], f2, __double_as_longlong(a1.x));
                FMA2(pY[1][1], f2, __double_as_longlong(a1.y));
                FMA2(pY[1][2], f2, __double_as_longlong(b1.x));
                FMA2(pY[1][3], f2, __double_as_longlong(b1.y));
            }
#pragma unroll
            for (int mu = 0; mu < 2; mu++) {
                float sm = sS[(m0 + mu)*32 + tx];
                unsigned long long s2; PACK2(s2, sm);
                const float* pr = sP + (m0 + mu)*64 + (ty << 3);
                double2 pa = *(const double2*)pr;
                double2 pb = *(const double2*)(pr + 4);
                FMA2(acc[0], s2, pY[mu][0]);
                FMA2(acc[1], s2, pY[mu][1]);
                FMA2(acc[2], s2, pY[mu][2]);
                FMA2(acc[3], s2, pY[mu][3]);
                FMA2(qcc[0], s2, __double_as_longlong(pa.x));
                FMA2(qcc[1], s2, __double_as_longlong(pa.y));
                FMA2(qcc[2], s2, __double_as_longlong(pb.x));
                FMA2(qcc[3], s2, __double_as_longlong(pb.y));
            }
        }

        int obase = ((b*64 + (ty << 3))*NP + n)*KK + tx;
#pragma unroll
        for (int j = 0; j < 4; j++) {
            float a0, a1, q0, q1;
            UNPACK2(a0, a1, acc[j]);
            UNPACK2(q0, q1, qcc[j]);
            int o = (ty << 3) + 2*j;
            out[obase + (2*j)*NP*KK]     = fmaxf(a0 - q0 + sB[o],     0.f);
            out[obase + (2*j + 1)*NP*KK] = fmaxf(a1 - q1 + sB[o + 1], 0.f);
        }
    }
}

extern "C" void kernel_launch(void* const* d_in, const int* in_sizes, int n_in,
                              void* d_out, int out_size)
{
    const float* features = (const float*)d_in[0];
    const float* pts      = (const float*)d_in[1];
    const float* w1  = (const float*)d_in[2];
    const float* g1  = (const float*)d_in[3];
    const float* be1 = (const float*)d_in[4];
    const float* w2  = (const float*)d_in[5];
    const float* g2  = (const float*)d_in[6];
    const float* be2 = (const float*)d_in[7];
    const float* w3  = (const float*)d_in[8];
    const float* g3  = (const float*)d_in[9];
    const float* be3 = (const float*)d_in[10];
    const float* w4  = (const float*)d_in[11];
    const float* b4  = (const float*)d_in[12];
    const float* wb  = (const float*)d_in[13];
    const float* bng = (const float*)d_in[14];
    const float* bnb = (const float*)d_in[15];
    float* out = (float*)d_out;

    const int P_SMEM    = CIN*MM*CO*4;                     // 131072
    const int MAIN_SMEM = (32768 + 2048 + 256 + 512 + 64)*4; // 142592
    cudaFuncSetAttribute(p_kernel,    cudaFuncAttributeMaxDynamicSharedMemorySize, P_SMEM);
    cudaFuncSetAttribute(main_kernel, cudaFuncAttributeMaxDynamicSharedMemorySize, MAIN_SMEM);

    reset_kernel<<<1, 32>>>();
    prep_kernel<<<(CIN*MM*CO + 255)/256, 256>>>(wb, bng);
    scores_kernel<<<(BB*NP*KK)/256, 256>>>(pts, w1, g1, be1, w2, g2, be2,
                                           w3, g3, be3, w4, b4);
    p_kernel<<<256, 256, P_SMEM>>>(features, wb, bng);
    main_kernel<<<256, 256, MAIN_SMEM>>>(features, bnb, out);
}

// round 2
// speedup vs baseline: 1.3245x; 1.3245x over previous
#include <cuda_runtime.h>
#include <math.h>

#define BB 8
#define CIN 64
#define NP 1024
#define KK 32
#define MM 8
#define CO 64
#define TILES (BB*NP)
#define NSM 148

typedef unsigned long long ull;

// device scratch (no allocations allowed)
__device__ float g_Wp[CIN*MM*CO];        // (c*8+m)*64+o, scaled by bn_g[o]/sqrt(1+eps)
__device__ float g_scores[BB*NP*KK*MM];  // ((b*N+n)*K+k)*8+m
__device__ float g_P[BB*NP*MM*CO];       // ((b*N+n)*8+m)*64+o, scaled
__device__ int   g_ctr[2];

#define FMA2(d,a,b)  asm("fma.rn.f32x2 %0, %1, %2, %0;" : "+l"(d) : "l"(a), "l"(b))
#define PACK2(d,x)   asm("mov.b64 %0, {%1, %1};" : "=l"(d) : "f"(x))
#define UNPACK2(lo,hi,v) asm("mov.b64 {%0, %1}, %2;" : "=f"(lo), "=f"(hi) : "l"(v))

__global__ void reset_kernel() {
    if (threadIdx.x < 2) g_ctr[threadIdx.x] = 0;
}

// W'[c,m,o] = (wb[c,m,o] + wb[c+64,m,o]) * bn_g[o]/sqrt(1+eps)
__global__ void prep_kernel(const float* __restrict__ wb, const float* __restrict__ bng) {
    int i = blockIdx.x*blockDim.x + threadIdx.x;
    if (i < CIN*MM*CO) {
        float sc = bng[i & 63] * rsqrtf(1.f + 1e-5f);
        g_Wp[i] = (wb[i] + wb[i + CIN*MM*CO]) * sc;
    }
}

// per-point score MLP + softmax
__global__ void scores_kernel(const float* __restrict__ pts,
    const float* __restrict__ w1, const float* __restrict__ g1, const float* __restrict__ be1,
    const float* __restrict__ w2, const float* __restrict__ g2, const float* __restrict__ be2,
    const float* __restrict__ w3, const float* __restrict__ g3, const float* __restrict__ be3,
    const float* __restrict__ w4, const float* __restrict__ b4)
{
    __shared__ float sw1[112], sw2[256], sw3[256], sw4[128];
    __shared__ float sc1[16], sb1[16], sc2[16], sb2[16], sc3[16], sb3[16], sb4[8];
    int t = threadIdx.x;
    float inv = rsqrtf(1.f + 1e-5f);
    if (t < 112) sw1[t] = w1[t];
    if (t < 256) { sw2[t] = w2[t]; sw3[t] = w3[t]; }
    if (t < 128) sw4[t] = w4[t];
    if (t < 16)  { sc1[t] = g1[t]*inv; sb1[t] = be1[t];
                   sc2[t] = g2[t]*inv; sb2[t] = be2[t];
                   sc3[t] = g3[t]*inv; sb3[t] = be3[t]; }
    if (t < 8)   sb4[t] = b4[t];
    __syncthreads();

    int p  = blockIdx.x*256 + t;
    int k  = p & 31;
    int bn = p >> 5;
    int n  = bn & 1023;
    int b  = bn >> 10;

    float xf[7];
    float d2 = 0.f;
#pragma unroll
    for (int d = 0; d < 3; d++) {
        int base = ((b*3 + d)*NP + n)*KK;
        float x  = pts[base + k];
        float cx = pts[base];
        xf[d] = cx;
        float df = x - cx;
        xf[3 + d] = df;
        d2 += df*df;
    }
    xf[6] = sqrtf(d2);

    float h1[16];
#pragma unroll
    for (int i = 0; i < 16; i++) {
        float a = 0.f;
#pragma unroll
        for (int j = 0; j < 7; j++) a += sw1[i*7 + j]*xf[j];
        h1[i] = fmaxf(a*sc1[i] + sb1[i], 0.f);
    }
    float h2[16];
#pragma unroll
    for (int i = 0; i < 16; i++) {
        float a = 0.f;
#pragma unroll
        for (int j = 0; j < 16; j++) a += sw2[i*16 + j]*h1[j];
        h2[i] = fmaxf(a*sc2[i] + sb2[i], 0.f);
    }
    float h3[16];
#pragma unroll
    for (int i = 0; i < 16; i++) {
        float a = 0.f;
#pragma unroll
        for (int j = 0; j < 16; j++) a += sw3[i*16 + j]*h2[j];
        h3[i] = fmaxf(a*sc3[i] + sb3[i], 0.f);
    }
    float s[8];
#pragma unroll
    for (int i = 0; i < 8; i++) {
        float a = sb4[i];
#pragma unroll
        for (int j = 0; j < 16; j++) a += sw4[i*16 + j]*h3[j];
        s[i] = a;
    }
    float mx = s[0];
#pragma unroll
    for (int i = 1; i < 8; i++) mx = fmaxf(mx, s[i]);
    float sum = 0.f;
#pragma unroll
    for (int i = 0; i < 8; i++) { s[i] = __expf(s[i] - mx); sum += s[i]; }
    float r = 1.f / sum;
    float4 v0 = make_float4(s[0]*r, s[1]*r, s[2]*r, s[3]*r);
    float4 v1 = make_float4(s[4]*r, s[5]*r, s[6]*r, s[7]*r);
    ((float4*)(g_scores + p*8))[0] = v0;
    ((float4*)(g_scores + p*8))[1] = v1;
}

// P[b,n,m,o] = sum_c center_feat[b,c,n] * wb_top'[c,m,o]   (persistent, 16 tiles/batch)
__global__ void __launch_bounds__(256, 1)
p_kernel(const float* __restrict__ feat, const float* __restrict__ wb,
         const float* __restrict__ bng)
{
    extern __shared__ float swb[];   // 32768 floats = 128KB pre-scaled wb_top
    __shared__ ull cen2[16*64];      // duplicated f32x2 pairs
    __shared__ int s_batch;
    int t = threadIdx.x;
    float inv = rsqrtf(1.f + 1e-5f);
    for (int i = t; i < CIN*MM*CO; i += 256) swb[i] = wb[i]*bng[i & 63]*inv;
    for (;;) {
        __syncthreads();
        if (t == 0) s_batch = atomicAdd(&g_ctr[0], 1);
        __syncthreads();
        int batch = s_batch;
        if (batch >= TILES/16) break;
        int tile0 = batch*16;
#pragma unroll
        for (int r = 0; r < 4; r++) {
            int i = t + r*256;
            int tl = i >> 6, c = i & 63;
            int tile = tile0 + tl;
            int b = tile >> 10, n = tile & 1023;
            float v = feat[((b*64 + c)*NP + n)*KK];   // k=0
            ull d; PACK2(d, v);
            cen2[tl*64 + c] = d;
        }
        __syncthreads();
        ull accp[16] = {};
#pragma unroll 4
        for (int c = 0; c < 64; c++) {
            ull w2 = *(const ull*)(swb + c*512 + 2*t);
#pragma unroll
            for (int tl = 0; tl < 16; tl++)
                FMA2(accp[tl], cen2[tl*64 + c], w2);
        }
#pragma unroll
        for (int tl = 0; tl < 16; tl++)
            *(ull*)(g_P + (tile0 + tl)*512 + 2*t) = accp[tl];
    }
}

// main: 2 tiles per pass. Y[m,o,k]=sum_c f[c,k]W'[c,m,o]; out=relu(sum_m s*(Y-P)+bn_b)
__global__ void __launch_bounds__(256, 1)
main_kernel(const float* __restrict__ feat, const float* __restrict__ bnb,
            float* __restrict__ out)
{
    extern __shared__ float smem[];
    float* sW = smem;            // 32768 : W' [c*512 + m*64 + o]
    float* sf = sW + 32768;      // 4096  : f  [c*64 + tl*32 + k]
    float* sS = sf + 4096;       // 512   : scores [tl*256 + m*32 + k]
    float* sP = sS + 512;        // 1024  : P [tl*512 + m*64 + o]
    float* sB = sP + 1024;       // 64    : bn beta
    __shared__ int s_pass;

    int t  = threadIdx.x;
    int tx = t & 31, ty = t >> 5;

    for (int i = t; i < 8192; i += 256)
        ((float4*)sW)[i] = ((const float4*)g_Wp)[i];
    if (t < 64) sB[t] = bnb[t];

    for (;;) {
        __syncthreads();
        if (t == 0) s_pass = atomicAdd(&g_ctr[1], 1);
        __syncthreads();
        int pass = s_pass;
        if (pass >= TILES/2) break;
        int tile0 = pass*2;
        int b = tile0 >> 10, n0 = tile0 & 1023;

        // f: two consecutive-n tiles are contiguous (64 floats per c)
#pragma unroll
        for (int r = 0; r < 4; r++) {
            int i = t + r*256;       // 0..1023 float4s
            int c = i >> 4, q = i & 15;
            *(float4*)(sf + c*64 + q*4) =
                *(const float4*)(feat + ((b*64 + c)*NP + n0)*KK + q*4);
        }
#pragma unroll
        for (int r = 0; r < 2; r++) {
            int i = t + r*256;       // 0..511
            int tl = i >> 8, j = i & 255;
            sS[tl*256 + (j & 7)*32 + (j >> 3)] = g_scores[tile0*256 + i];
        }
#pragma unroll
        for (int r = 0; r < 4; r++)
            sP[t + r*256] = g_P[tile0*512 + t + r*256];
        __syncthreads();

        ull acc[2][4] = {{0,0,0,0},{0,0,0,0}};
        ull qcc[2][4] = {{0,0,0,0},{0,0,0,0}};

#pragma unroll
        for (int m0 = 0; m0 < 8; m0 += 2) {
            ull pY[2][2][4] = {{{0,0,0,0},{0,0,0,0}},{{0,0,0,0},{0,0,0,0}}};
#pragma unroll 2
            for (int c = 0; c < 64; c++) {
                float f0 = sf[c*64 + tx];
                float f1 = sf[c*64 + 32 + tx];
                ull f20, f21; PACK2(f20, f0); PACK2(f21, f1);
                const float* wr = sW + c*512 + m0*64 + (ty << 3);
                double2 wa0 = *(const double2*)wr;
                double2 wb0 = *(const double2*)(wr + 4);
                double2 wa1 = *(const double2*)(wr + 64);
                double2 wb1 = *(const double2*)(wr + 68);
                ull w00 = __double_as_longlong(wa0.x), w01 = __double_as_longlong(wa0.y);
                ull w02 = __double_as_longlong(wb0.x), w03 = __double_as_longlong(wb0.y);
                ull w10 = __double_as_longlong(wa1.x), w11 = __double_as_longlong(wa1.y);
                ull w12 = __double_as_longlong(wb1.x), w13 = __double_as_longlong(wb1.y);
                FMA2(pY[0][0][0], f20, w00); FMA2(pY[0][0][1], f20, w01);
                FMA2(pY[0][0][2], f20, w02); FMA2(pY[0][0][3], f20, w03);
                FMA2(pY[0][1][0], f20, w10); FMA2(pY[0][1][1], f20, w11);
                FMA2(pY[0][1][2], f20, w12); FMA2(pY[0][1][3], f20, w13);
                FMA2(pY[1][0][0], f21, w00); FMA2(pY[1][0][1], f21, w01);
                FMA2(pY[1][0][2], f21, w02); FMA2(pY[1][0][3], f21, w03);
                FMA2(pY[1][1][0], f21, w10); FMA2(pY[1][1][1], f21, w11);
                FMA2(pY[1][1][2], f21, w12); FMA2(pY[1][1][3], f21, w13);
            }
#pragma unroll
            for (int mu = 0; mu < 2; mu++) {
                int m = m0 + mu;
#pragma unroll
                for (int tl = 0; tl < 2; tl++) {
                    float sm = sS[tl*256 + m*32 + tx];
                    ull s2; PACK2(s2, sm);
                    FMA2(acc[tl][0], s2, pY[tl][mu][0]);
                    FMA2(acc[tl][1], s2, pY[tl][mu][1]);
                    FMA2(acc[tl][2], s2, pY[tl][mu][2]);
                    FMA2(acc[tl][3], s2, pY[tl][mu][3]);
                    const float* pr = sP + tl*512 + m*64 + (ty << 3);
                    double2 pa = *(const double2*)pr;
                    double2 pb = *(const double2*)(pr + 4);
                    FMA2(qcc[tl][0], s2, __double_as_longlong(pa.x));
                    FMA2(qcc[tl][1], s2, __double_as_longlong(pa.y));
                    FMA2(qcc[tl][2], s2, __double_as_longlong(pb.x));
                    FMA2(qcc[tl][3], s2, __double_as_longlong(pb.y));
                }
            }
        }

#pragma unroll
        for (int tl = 0; tl < 2; tl++) {
            int obase = ((b*64 + (ty << 3))*NP + (n0 + tl))*KK + tx;
#pragma unroll
            for (int j = 0; j < 4; j++) {
                float a0, a1, q0, q1;
                UNPACK2(a0, a1, acc[tl][j]);
                UNPACK2(q0, q1, qcc[tl][j]);
                int o = (ty << 3) + 2*j;
                out[obase + (2*j)*NP*KK]     = fmaxf(a0 - q0 + sB[o],     0.f);
                out[obase + (2*j + 1)*NP*KK] = fmaxf(a1 - q1 + sB[o + 1], 0.f);
            }
        }
    }
}

extern "C" void kernel_launch(void* const* d_in, const int* in_sizes, int n_in,
                              void* d_out, int out_size)
{
    const float* features = (const float*)d_in[0];
    const float* pts      = (const float*)d_in[1];
    const float* w1  = (const float*)d_in[2];
    const float* g1  = (const float*)d_in[3];
    const float* be1 = (const float*)d_in[4];
    const float* w2  = (const float*)d_in[5];
    const float* g2  = (const float*)d_in[6];
    const float* be2 = (const float*)d_in[7];
    const float* w3  = (const float*)d_in[8];
    const float* g3  = (const float*)d_in[9];
    const float* be3 = (const float*)d_in[10];
    const float* w4  = (const float*)d_in[11];
    const float* b4  = (const float*)d_in[12];
    const float* wb  = (const float*)d_in[13];
    const float* bng = (const float*)d_in[14];
    const float* bnb = (const float*)d_in[15];
    float* out = (float*)d_out;

    const int P_SMEM    = CIN*MM*CO*4;                         // 131072
    const int MAIN_SMEM = (32768 + 4096 + 512 + 1024 + 64)*4;  // 153856
    cudaFuncSetAttribute(p_kernel,    cudaFuncAttributeMaxDynamicSharedMemorySize, P_SMEM);
    cudaFuncSetAttribute(main_kernel, cudaFuncAttributeMaxDynamicSharedMemorySize, MAIN_SMEM);

    reset_kernel<<<1, 32>>>();
    prep_kernel<<<(CIN*MM*CO + 255)/256, 256>>>(wb, bng);
    scores_kernel<<<(BB*NP*KK)/256, 256>>>(pts, w1, g1, be1, w2, g2, be2,
                                           w3, g3, be3, w4, b4);
    p_kernel<<<NSM, 256, P_SMEM>>>(features, wb, bng);
    main_kernel<<<NSM, 256, MAIN_SMEM>>>(features, bnb, out);
}

// round 3
// speedup vs baseline: 1.3249x; 1.0003x over previous
#include <cuda_runtime.h>
#include <math.h>

#define BB 8
#define CIN 64
#define NP 1024
#define KK 32
#define MM 8
#define CO 64
#define TILES (BB*NP)
#define NSM 148

typedef unsigned long long ull;

// device scratch (no allocations allowed)
__device__ float g_Wp[CIN*MM*CO];        // (c*8+m)*64+o, scaled by bn_g[o]/sqrt(1+eps)
__device__ float g_scores[BB*NP*KK*MM];  // ((b*N+n)*K+k)*8+m
__device__ float g_P[BB*NP*MM*CO];       // ((b*N+n)*8+m)*64+o, scaled
__device__ int   g_ctr[2];

#define FMA2(d,a,b)  asm("fma.rn.f32x2 %0, %1, %2, %0;" : "+l"(d) : "l"(a), "l"(b))
#define PACK2(d,x)   asm("mov.b64 %0, {%1, %1};" : "=l"(d) : "f"(x))
#define UNPACK2(lo,hi,v) asm("mov.b64 {%0, %1}, %2;" : "=f"(lo), "=f"(hi) : "l"(v))

__global__ void reset_kernel() {
    if (threadIdx.x < 2) g_ctr[threadIdx.x] = 0;
}

// W'[c,m,o] = (wb[c,m,o] + wb[c+64,m,o]) * bn_g[o]/sqrt(1+eps)
__global__ void prep_kernel(const float* __restrict__ wb, const float* __restrict__ bng) {
    int i = blockIdx.x*blockDim.x + threadIdx.x;
    if (i < CIN*MM*CO) {
        float sc = bng[i & 63] * rsqrtf(1.f + 1e-5f);
        g_Wp[i] = (wb[i] + wb[i + CIN*MM*CO]) * sc;
    }
}

// per-point score MLP + softmax
__global__ void scores_kernel(const float* __restrict__ pts,
    const float* __restrict__ w1, const float* __restrict__ g1, const float* __restrict__ be1,
    const float* __restrict__ w2, const float* __restrict__ g2, const float* __restrict__ be2,
    const float* __restrict__ w3, const float* __restrict__ g3, const float* __restrict__ be3,
    const float* __restrict__ w4, const float* __restrict__ b4)
{
    __shared__ float sw1[112], sw2[256], sw3[256], sw4[128];
    __shared__ float sc1[16], sb1[16], sc2[16], sb2[16], sc3[16], sb3[16], sb4[8];
    int t = threadIdx.x;
    float inv = rsqrtf(1.f + 1e-5f);
    if (t < 112) sw1[t] = w1[t];
    if (t < 256) { sw2[t] = w2[t]; sw3[t] = w3[t]; }
    if (t < 128) sw4[t] = w4[t];
    if (t < 16)  { sc1[t] = g1[t]*inv; sb1[t] = be1[t];
                   sc2[t] = g2[t]*inv; sb2[t] = be2[t];
                   sc3[t] = g3[t]*inv; sb3[t] = be3[t]; }
    if (t < 8)   sb4[t] = b4[t];
    __syncthreads();

    int p  = blockIdx.x*256 + t;
    int k  = p & 31;
    int bn = p >> 5;
    int n  = bn & 1023;
    int b  = bn >> 10;

    float xf[7];
    float d2 = 0.f;
#pragma unroll
    for (int d = 0; d < 3; d++) {
        int base = ((b*3 + d)*NP + n)*KK;
        float x  = pts[base + k];
        float cx = pts[base];
        xf[d] = cx;
        float df = x - cx;
        xf[3 + d] = df;
        d2 += df*df;
    }
    xf[6] = sqrtf(d2);

    float h1[16];
#pragma unroll
    for (int i = 0; i < 16; i++) {
        float a = 0.f;
#pragma unroll
        for (int j = 0; j < 7; j++) a += sw1[i*7 + j]*xf[j];
        h1[i] = fmaxf(a*sc1[i] + sb1[i], 0.f);
    }
    float h2[16];
#pragma unroll
    for (int i = 0; i < 16; i++) {
        float a = 0.f;
#pragma unroll
        for (int j = 0; j < 16; j++) a += sw2[i*16 + j]*h1[j];
        h2[i] = fmaxf(a*sc2[i] + sb2[i], 0.f);
    }
    float h3[16];
#pragma unroll
    for (int i = 0; i < 16; i++) {
        float a = 0.f;
#pragma unroll
        for (int j = 0; j < 16; j++) a += sw3[i*16 + j]*h2[j];
        h3[i] = fmaxf(a*sc3[i] + sb3[i], 0.f);
    }
    float s[8];
#pragma unroll
    for (int i = 0; i < 8; i++) {
        float a = sb4[i];
#pragma unroll
        for (int j = 0; j < 16; j++) a += sw4[i*16 + j]*h3[j];
        s[i] = a;
    }
    float mx = s[0];
#pragma unroll
    for (int i = 1; i < 8; i++) mx = fmaxf(mx, s[i]);
    float sum = 0.f;
#pragma unroll
    for (int i = 0; i < 8; i++) { s[i] = __expf(s[i] - mx); sum += s[i]; }
    float r = 1.f / sum;
    float4 v0 = make_float4(s[0]*r, s[1]*r, s[2]*r, s[3]*r);
    float4 v1 = make_float4(s[4]*r, s[5]*r, s[6]*r, s[7]*r);
    ((float4*)(g_scores + p*8))[0] = v0;
    ((float4*)(g_scores + p*8))[1] = v1;
}

// P[b,n,m,o] = sum_c center_feat[b,c,n] * wb_top'[c,m,o]   (persistent, 16 tiles/batch)
__global__ void __launch_bounds__(256, 1)
p_kernel(const float* __restrict__ feat, const float* __restrict__ wb,
         const float* __restrict__ bng)
{
    extern __shared__ float swb[];   // 32768 floats = 128KB pre-scaled wb_top
    __shared__ ull cen2[16*64];      // duplicated f32x2 pairs
    __shared__ int s_batch;
    int t = threadIdx.x;
    float inv = rsqrtf(1.f + 1e-5f);
    for (int i = t; i < CIN*MM*CO; i += 256) swb[i] = wb[i]*bng[i & 63]*inv;
    for (;;) {
        __syncthreads();
        if (t == 0) s_batch = atomicAdd(&g_ctr[0], 1);
        __syncthreads();
        int batch = s_batch;
        if (batch >= TILES/16) break;
        int tile0 = batch*16;
#pragma unroll
        for (int r = 0; r < 4; r++) {
            int i = t + r*256;
            int tl = i >> 6, c = i & 63;
            int tile = tile0 + tl;
            int b = tile >> 10, n = tile & 1023;
            float v = feat[((b*64 + c)*NP + n)*KK];   // k=0
            ull d; PACK2(d, v);
            cen2[tl*64 + c] = d;
        }
        __syncthreads();
        ull accp[16] = {};
#pragma unroll 4
        for (int c = 0; c < 64; c++) {
            ull w2 = *(const ull*)(swb + c*512 + 2*t);
#pragma unroll
            for (int tl = 0; tl < 16; tl++)
                FMA2(accp[tl], cen2[tl*64 + c], w2);
        }
#pragma unroll
        for (int tl = 0; tl < 16; tl++)
            *(ull*)(g_P + (tile0 + tl)*512 + 2*t) = accp[tl];
    }
}

// main: 2 tiles per pass. Y[m,o,k]=sum_c f[c,k]W'[c,m,o]; out=relu(sum_m s*(Y-P)+bn_b)
__global__ void __launch_bounds__(256, 1)
main_kernel(const float* __restrict__ feat, const float* __restrict__ bnb,
            float* __restrict__ out)
{
    extern __shared__ float smem[];
    float* sW = smem;            // 32768 : W' [c*512 + m*64 + o]
    float* sf = sW + 32768;      // 4096  : f  [c*64 + tl*32 + k]
    float* sS = sf + 4096;       // 512   : scores [tl*256 + m*32 + k]
    float* sP = sS + 512;        // 1024  : P [tl*512 + m*64 + o]
    float* sB = sP + 1024;       // 64    : bn beta
    __shared__ int s_pass;

    int t  = threadIdx.x;
    int tx = t & 31, ty = t >> 5;

    for (int i = t; i < 8192; i += 256)
        ((float4*)sW)[i] = ((const float4*)g_Wp)[i];
    if (t < 64) sB[t] = bnb[t];

    for (;;) {
        __syncthreads();
        if (t == 0) s_pass = atomicAdd(&g_ctr[1], 1);
        __syncthreads();
        int pass = s_pass;
        if (pass >= TILES/2) break;
        int tile0 = pass*2;
        int b = tile0 >> 10, n0 = tile0 & 1023;

        // f: two consecutive-n tiles are contiguous (64 floats per c)
#pragma unroll
        for (int r = 0; r < 4; r++) {
            int i = t + r*256;       // 0..1023 float4s
            int c = i >> 4, q = i & 15;
            *(float4*)(sf + c*64 + q*4) =
                *(const float4*)(feat + ((b*64 + c)*NP + n0)*KK + q*4);
        }
#pragma unroll
        for (int r = 0; r < 2; r++) {
            int i = t + r*256;       // 0..511
            int tl = i >> 8, j = i & 255;
            sS[tl*256 + (j & 7)*32 + (j >> 3)] = g_scores[tile0*256 + i];
        }
#pragma unroll
        for (int r = 0; r < 4; r++)
            sP[t + r*256] = g_P[tile0*512 + t + r*256];
        __syncthreads();

        ull acc[2][4] = {{0,0,0,0},{0,0,0,0}};
        ull qcc[2][4] = {{0,0,0,0},{0,0,0,0}};

#pragma unroll
        for (int m0 = 0; m0 < 8; m0 += 2) {
            ull pY[2][2][4] = {{{0,0,0,0},{0,0,0,0}},{{0,0,0,0},{0,0,0,0}}};
#pragma unroll 2
            for (int c = 0; c < 64; c++) {
                float f0 = sf[c*64 + tx];
                float f1 = sf[c*64 + 32 + tx];
                ull f20, f21; PACK2(f20, f0); PACK2(f21, f1);
                const float* wr = sW + c*512 + m0*64 + (ty << 3);
                double2 wa0 = *(const double2*)wr;
                double2 wb0 = *(const double2*)(wr + 4);
                double2 wa1 = *(const double2*)(wr + 64);
                double2 wb1 = *(const double2*)(wr + 68);
                ull w00 = __double_as_longlong(wa0.x), w01 = __double_as_longlong(wa0.y);
                ull w02 = __double_as_longlong(wb0.x), w03 = __double_as_longlong(wb0.y);
                ull w10 = __double_as_longlong(wa1.x), w11 = __double_as_longlong(wa1.y);
                ull w12 = __double_as_longlong(wb1.x), w13 = __double_as_longlong(wb1.y);
                FMA2(pY[0][0][0], f20, w00); FMA2(pY[0][0][1], f20, w01);
                FMA2(pY[0][0][2], f20, w02); FMA2(pY[0][0][3], f20, w03);
                FMA2(pY[0][1][0], f20, w10); FMA2(pY[0][1][1], f20, w11);
                FMA2(pY[0][1][2], f20, w12); FMA2(pY[0][1][3], f20, w13);
                FMA2(pY[1][0][0], f21, w00); FMA2(pY[1][0][1], f21, w01);
                FMA2(pY[1][0][2], f21, w02); FMA2(pY[1][0][3], f21, w03);
                FMA2(pY[1][1][0], f21, w10); FMA2(pY[1][1][1], f21, w11);
                FMA2(pY[1][1][2], f21, w12); FMA2(pY[1][1][3], f21, w13);
            }
#pragma unroll
            for (int mu = 0; mu < 2; mu++) {
                int m = m0 + mu;
#pragma unroll
                for (int tl = 0; tl < 2; tl++) {
                    float sm = sS[tl*256 + m*32 + tx];
                    ull s2; PACK2(s2, sm);
                    FMA2(acc[tl][0], s2, pY[tl][mu][0]);
                    FMA2(acc[tl][1], s2, pY[tl][mu][1]);
                    FMA2(acc[tl][2], s2, pY[tl][mu][2]);
                    FMA2(acc[tl][3], s2, pY[tl][mu][3]);
                    const float* pr = sP + tl*512 + m*64 + (ty << 3);
                    double2 pa = *(const double2*)pr;
                    double2 pb = *(const double2*)(pr + 4);
                    FMA2(qcc[tl][0], s2, __double_as_longlong(pa.x));
                    FMA2(qcc[tl][1], s2, __double_as_longlong(pa.y));
                    FMA2(qcc[tl][2], s2, __double_as_longlong(pb.x));
                    FMA2(qcc[tl][3], s2, __double_as_longlong(pb.y));
                }
            }
        }

#pragma unroll
        for (int tl = 0; tl < 2; tl++) {
            int obase = ((b*64 + (ty << 3))*NP + (n0 + tl))*KK + tx;
#pragma unroll
            for (int j = 0; j < 4; j++) {
                float a0, a1, q0, q1;
                UNPACK2(a0, a1, acc[tl][j]);
                UNPACK2(q0, q1, qcc[tl][j]);
                int o = (ty << 3) + 2*j;
                out[obase + (2*j)*NP*KK]     = fmaxf(a0 - q0 + sB[o],     0.f);
                out[obase + (2*j + 1)*NP*KK] = fmaxf(a1 - q1 + sB[o + 1], 0.f);
            }
        }
    }
}

extern "C" void kernel_launch(void* const* d_in, const int* in_sizes, int n_in,
                              void* d_out, int out_size)
{
    const float* features = (const float*)d_in[0];
    const float* pts      = (const float*)d_in[1];
    const float* w1  = (const float*)d_in[2];
    const float* g1  = (const float*)d_in[3];
    const float* be1 = (const float*)d_in[4];
    const float* w2  = (const float*)d_in[5];
    const float* g2  = (const float*)d_in[6];
    const float* be2 = (const float*)d_in[7];
    const float* w3  = (const float*)d_in[8];
    const float* g3  = (const float*)d_in[9];
    const float* be3 = (const float*)d_in[10];
    const float* w4  = (const float*)d_in[11];
    const float* b4  = (const float*)d_in[12];
    const float* wb  = (const float*)d_in[13];
    const float* bng = (const float*)d_in[14];
    const float* bnb = (const float*)d_in[15];
    float* out = (float*)d_out;

    const int P_SMEM    = CIN*MM*CO*4;                         // 131072
    const int MAIN_SMEM = (32768 + 4096 + 512 + 1024 + 64)*4;  // 153856
    cudaFuncSetAttribute(p_kernel,    cudaFuncAttributeMaxDynamicSharedMemorySize, P_SMEM);
    cudaFuncSetAttribute(main_kernel, cudaFuncAttributeMaxDynamicSharedMemorySize, MAIN_SMEM);

    reset_kernel<<<1, 32>>>();
    prep_kernel<<<(CIN*MM*CO + 255)/256, 256>>>(wb, bng);
    scores_kernel<<<(BB*NP*KK)/256, 256>>>(pts, w1, g1, be1, w2, g2, be2,
                                           w3, g3, be3, w4, b4);
    p_kernel<<<NSM, 256, P_SMEM>>>(features, wb, bng);
    main_kernel<<<NSM, 256, MAIN_SMEM>>>(features, bnb, out);
}

// round 5
// speedup vs baseline: 2.9825x; 2.2511x over previous
#include <cuda_runtime.h>
#include <math.h>
#include <stdint.h>

typedef unsigned long long ull;
typedef unsigned int u32;

#define NP 1024
#define KK 32
#define TILES 8192
#define NPASS 4096
#define GRID 148

// ---------------- device scratch ----------------
__device__ float g_A[512*68];         // W2' tf32, rows mo'=o*8+m, stride 68, cols c
__device__ float g_cen[64*TILES];     // [c][bn]
__device__ float g_scores[TILES*256]; // [tile][k][m]
__device__ float g_P[TILES*512];      // [tile][m*64+o]  (fp32, bn_g-scaled)

#define FMA2(d,a,b)  asm("fma.rn.f32x2 %0, %1, %2, %0;" : "+l"(d) : "l"(a), "l"(b))
#define PACK2(d,x)   asm("mov.b64 %0, {%1, %1};" : "=l"(d) : "f"(x))

__device__ __forceinline__ float tf32r(float x) {
    float r; asm("cvt.rna.tf32.f32 %0, %1;" : "=f"(r) : "f"(x)); return r;
}
__device__ __forceinline__ void mma8(float* d, u32 a0, u32 a1, u32 a2, u32 a3,
                                     u32 b0, u32 b1) {
    asm volatile(
        "mma.sync.aligned.m16n8k8.row.col.f32.tf32.tf32.f32 "
        "{%0,%1,%2,%3}, {%4,%5,%6,%7}, {%8,%9}, {%0,%1,%2,%3};"
        : "+f"(d[0]), "+f"(d[1]), "+f"(d[2]), "+f"(d[3])
        : "r"(a0), "r"(a1), "r"(a2), "r"(a3), "r"(b0), "r"(b1));
}

// ---------------- prep: A = tf32(W2') rows mo'=o*8+m ----------------
__global__ void prepA_kernel(const float* __restrict__ wb, const float* __restrict__ bng) {
    int i = blockIdx.x*256 + threadIdx.x;      // i = c*512 + m*64 + o
    int c = i >> 9, rem = i & 511;
    int m = rem >> 6, o = rem & 63;
    float v = (wb[i] + wb[i + 32768]) * bng[o] * rsqrtf(1.f + 1e-5f);
    g_A[(o*8 + m)*68 + c] = tf32r(v);
}

// ---------------- gather center features ----------------
__global__ void gather_kernel(const float* __restrict__ feat) {
    int i = blockIdx.x*256 + threadIdx.x;      // < 64*8192
    int c = i >> 13; int bn = i & 8191;
    int b = bn >> 10, n = bn & 1023;
    g_cen[i] = feat[((b*64 + c)*NP + n)*KK];   // k = 0
}

// ---------------- score MLP + softmax ----------------
__global__ void scores_kernel(const float* __restrict__ pts,
    const float* __restrict__ w1, const float* __restrict__ g1, const float* __restrict__ be1,
    const float* __restrict__ w2, const float* __restrict__ g2, const float* __restrict__ be2,
    const float* __restrict__ w3, const float* __restrict__ g3, const float* __restrict__ be3,
    const float* __restrict__ w4, const float* __restrict__ b4)
{
    __shared__ float sw1[112], sw2[256], sw3[256], sw4[128];
    __shared__ float sc1[16], sb1[16], sc2[16], sb2[16], sc3[16], sb3[16], sb4[8];
    int t = threadIdx.x;
    float inv = rsqrtf(1.f + 1e-5f);
    if (t < 112) sw1[t] = w1[t];
    if (t < 256) { sw2[t] = w2[t]; sw3[t] = w3[t]; }
    if (t < 128) sw4[t] = w4[t];
    if (t < 16)  { sc1[t] = g1[t]*inv; sb1[t] = be1[t];
                   sc2[t] = g2[t]*inv; sb2[t] = be2[t];
                   sc3[t] = g3[t]*inv; sb3[t] = be3[t]; }
    if (t < 8)   sb4[t] = b4[t];
    __syncthreads();

    int p  = blockIdx.x*256 + t;
    int k  = p & 31;
    int bn = p >> 5;
    int n  = bn & 1023;
    int b  = bn >> 10;

    float xf[7];
    float d2 = 0.f;
#pragma unroll
    for (int d = 0; d < 3; d++) {
        int base = ((b*3 + d)*NP + n)*KK;
        float x  = pts[base + k];
        float cx = pts[base];
        xf[d] = cx;
        float df = x - cx;
        xf[3 + d] = df;
        d2 += df*df;
    }
    xf[6] = sqrtf(d2);

    float h1[16];
#pragma unroll
    for (int i = 0; i < 16; i++) {
        float a = 0.f;
#pragma unroll
        for (int j = 0; j < 7; j++) a += sw1[i*7 + j]*xf[j];
        h1[i] = fmaxf(a*sc1[i] + sb1[i], 0.f);
    }
    float h2[16];
#pragma unroll
    for (int i = 0; i < 16; i++) {
        float a = 0.f;
#pragma unroll
        for (int j = 0; j < 16; j++) a += sw2[i*16 + j]*h1[j];
        h2[i] = fmaxf(a*sc2[i] + sb2[i], 0.f);
    }
    float h3[16];
#pragma unroll
    for (int i = 0; i < 16; i++) {
        float a = 0.f;
#pragma unroll
        for (int j = 0; j < 16; j++) a += sw3[i*16 + j]*h2[j];
        h3[i] = fmaxf(a*sc3[i] + sb3[i], 0.f);
    }
    float s[8];
#pragma unroll
    for (int i = 0; i < 8; i++) {
        float a = sb4[i];
#pragma unroll
        for (int j = 0; j < 16; j++) a += sw4[i*16 + j]*h3[j];
        s[i] = a;
    }
    float mx = s[0];
#pragma unroll
    for (int i = 1; i < 8; i++) mx = fmaxf(mx, s[i]);
    float sum = 0.f;
#pragma unroll
    for (int i = 0; i < 8; i++) { s[i] = __expf(s[i] - mx); sum += s[i]; }
    float r = 1.f / sum;
    float4 v0 = make_float4(s[0]*r, s[1]*r, s[2]*r, s[3]*r);
    float4 v1 = make_float4(s[4]*r, s[5]*r, s[6]*r, s[7]*r);
    ((float4*)(g_scores + p*8))[0] = v0;
    ((float4*)(g_scores + p*8))[1] = v1;
}

// ---------------- P GEMM (fp32 FFMA2, 16 tiles/batch, static partition) ----------------
__global__ void __launch_bounds__(256, 1)
p_kernel(const float* __restrict__ wb, const float* __restrict__ bng)
{
    extern __shared__ float swb[];   // 32768 floats = 128KB pre-scaled wb_top
    __shared__ ull cen2[16*65];
    int t = threadIdx.x;
    float inv = rsqrtf(1.f + 1e-5f);
    for (int i = t; i < 32768; i += 256) swb[i] = wb[i]*bng[i & 63]*inv;
    __syncthreads();
    for (int batch = blockIdx.x; batch < TILES/16; batch += GRID) {
        int tile0 = batch*16;
#pragma unroll
        for (int r = 0; r < 4; r++) {
            int i = t + r*256;              // 0..1023
            int c = i >> 4, tl = i & 15;
            float v = g_cen[c*8192 + tile0 + tl];
            ull d; PACK2(d, v);
            cen2[tl*65 + c] = d;
        }
        __syncthreads();
        ull accp[16] = {};
#pragma unroll 4
        for (int c = 0; c < 64; c++) {
            ull w2 = *(const ull*)(swb + c*512 + 2*t);
#pragma unroll
            for (int tl = 0; tl < 16; tl++)
                FMA2(accp[tl], cen2[tl*65 + c], w2);
        }
#pragma unroll
        for (int tl = 0; tl < 16; tl++)
            *(ull*)(g_P + (tile0 + tl)*512 + 2*t) = accp[tl];
        __syncthreads();
    }
}

// ---------------- main: mma.sync tf32 GEMM + fused epilogue ----------------
// smem floats: sA[0,34816) stride-68 W'; sF[34816,39936) f 2 tiles stride 40;
//              sS[39936,40464) scores [tl][m*33+k]; sP[40464,41488) [tl][o*8+m];
//              sBnb[41488,41552)
__global__ void __launch_bounds__(256, 1)
main_kernel(const float* __restrict__ feat, const float* __restrict__ bnb,
            float* __restrict__ out)
{
    extern __shared__ float sm[];
    float* sA   = sm;
    float* sF   = sm + 34816;
    float* sS   = sm + 39936;
    float* sP   = sm + 40464;
    float* sBnb = sm + 41488;

    int t = threadIdx.x;
    int w = t >> 5, lane = t & 31;
    int g = lane >> 2, tid = lane & 3;
    int Rw = w*64;                    // this warp's A row base (o = w*8 .. w*8+7)

    // prologue: copy A (stationary), bnb
#pragma unroll 8
    for (int i = 0; i < 34; i++)
        ((float4*)sA)[t + i*256] = ((const float4*)g_A)[t + i*256];
    if (t < 64) sBnb[t] = bnb[t];

    int cnt = (NPASS - 1 - (int)blockIdx.x)/GRID + 1;

    float4 rf[4]; float rs[2]; float rp[4];

    auto stage_ldg = [&](int pp) {
        int tile0 = pp*2; int b = tile0 >> 10; int n0 = tile0 & 1023;
        const float* fbase = feat + ((b*64)*NP + n0)*KK;
#pragma unroll
        for (int j = 0; j < 4; j++) {
            int idx = t + j*256;
            int c = idx >> 4, q = idx & 15;
            rf[j] = *(const float4*)(fbase + c*NP*KK + q*4);
        }
#pragma unroll
        for (int j = 0; j < 2; j++) rs[j] = g_scores[tile0*256 + t + j*256];
#pragma unroll
        for (int j = 0; j < 4; j++) rp[j] = g_P[tile0*512 + t + j*256];
    };
    auto stage_sts = [&]() {
#pragma unroll
        for (int j = 0; j < 4; j++) {
            int idx = t + j*256;
            int c = idx >> 4, q = idx & 15;
            int tl = q >> 3, k4 = (q & 7)*4;
            float4 v = rf[j];
            v.x = tf32r(v.x); v.y = tf32r(v.y); v.z = tf32r(v.z); v.w = tf32r(v.w);
            *(float4*)(sF + tl*2560 + c*40 + k4) = v;
        }
#pragma unroll
        for (int j = 0; j < 2; j++) {
            int idx = t + j*256;            // tl*256 + k*8 + m
            int tl = idx >> 8, rem = idx & 255;
            int k = rem >> 3, m = rem & 7;
            sS[tl*264 + m*33 + k] = rs[j];
        }
#pragma unroll
        for (int j = 0; j < 4; j++) {
            int idx = t + j*256;            // tl*512 + m*64 + o
            int tl = idx >> 9, rem = idx & 511;
            int m = rem >> 6, o = rem & 63;
            sP[tl*512 + o*8 + m] = rp[j];
        }
    };

    stage_ldg(blockIdx.x);

    int cp = blockIdx.x;
    for (int it = 0; it < cnt; it++, cp += GRID) {
        stage_sts();
        __syncthreads();
        if (it + 1 < cnt) stage_ldg(cp + GRID);   // overlaps with compute

        int tile0 = cp*2;
        int b = tile0 >> 10, n0 = tile0 & 1023;

#pragma unroll
        for (int h2 = 0; h2 < 2; h2++) {          // h2 == tile index
            const float* sFh = sF + h2*2560;
            float acc[4][4][4];
#pragma unroll
            for (int mt = 0; mt < 4; mt++)
#pragma unroll
                for (int nt = 0; nt < 4; nt++)
#pragma unroll
                    for (int r = 0; r < 4; r++) acc[mt][nt][r] = 0.f;

#pragma unroll
            for (int ks = 0; ks < 8; ks++) {
                u32 bf[4][2];
#pragma unroll
                for (int nt = 0; nt < 4; nt++) {
                    int cc = ks*8 + tid;
                    bf[nt][0] = __float_as_uint(sFh[cc*40 + nt*8 + g]);
                    bf[nt][1] = __float_as_uint(sFh[(cc + 4)*40 + nt*8 + g]);
                }
#pragma unroll
                for (int mt = 0; mt < 4; mt++) {
                    int R = Rw + mt*16;
                    const float* ar = sA + (R + g)*68 + ks*8 + tid;
                    u32 a0 = __float_as_uint(ar[0]);
                    u32 a1 = __float_as_uint(ar[8*68]);
                    u32 a2 = __float_as_uint(ar[4]);
                    u32 a3 = __float_as_uint(ar[8*68 + 4]);
#pragma unroll
                    for (int nt = 0; nt < 4; nt++)
                        mma8(acc[mt][nt], a0, a1, a2, a3, bf[nt][0], bf[nt][1]);
                }
            }

            // epilogue: out[o,k] = relu( sum_m s[m,k]*(Y[m,o,k]-P[m,o]) + bnb[o] )
            int n = n0 + h2;
            float s0v[4], s1v[4];
#pragma unroll
            for (int nt = 0; nt < 4; nt++) {
                s0v[nt] = sS[h2*264 + g*33 + nt*8 + 2*tid];
                s1v[nt] = sS[h2*264 + g*33 + nt*8 + 2*tid + 1];
            }
#pragma unroll
            for (int mt = 0; mt < 4; mt++) {
                int o0 = w*8 + mt*2;
                float p0 = sP[h2*512 + o0*8 + g];
                float p1 = sP[h2*512 + (o0 + 1)*8 + g];
#pragma unroll
                for (int nt = 0; nt < 4; nt++) {
                    float v0 = (acc[mt][nt][0] - p0)*s0v[nt];
                    float v1 = (acc[mt][nt][1] - p0)*s1v[nt];
                    float v2 = (acc[mt][nt][2] - p1)*s0v[nt];
                    float v3 = (acc[mt][nt][3] - p1)*s1v[nt];
#pragma unroll
                    for (int d = 4; d < 32; d <<= 1) {
                        v0 += __shfl_xor_sync(0xffffffffu, v0, d);
                        v1 += __shfl_xor_sync(0xffffffffu, v1, d);
                        v2 += __shfl_xor_sync(0xffffffffu, v2, d);
                        v3 += __shfl_xor_sync(0xffffffffu, v3, d);
                    }
                    if (lane < 4) {
                        int k0 = h2*0 + nt*8 + 2*tid;     // k within tile
                        float b0 = sBnb[o0], b1 = sBnb[o0 + 1];
                        float2 r0 = make_float2(fmaxf(v0 + b0, 0.f), fmaxf(v1 + b0, 0.f));
                        float2 r1 = make_float2(fmaxf(v2 + b1, 0.f), fmaxf(v3 + b1, 0.f));
                        float* ob = out + ((b*64 + o0)*NP + n)*KK + k0;
                        *(float2*)ob = r0;
                        *(float2*)(ob + NP*KK) = r1;
                    }
                }
            }
        }
        __syncthreads();
    }
}

// ---------------- launch ----------------
extern "C" void kernel_launch(void* const* d_in, const int* in_sizes, int n_in,
                              void* d_out, int out_size)
{
    const float* features = (const float*)d_in[0];
    const float* pts      = (const float*)d_in[1];
    const float* w1  = (const float*)d_in[2];
    const float* g1  = (const float*)d_in[3];
    const float* be1 = (const float*)d_in[4];
    const float* w2  = (const float*)d_in[5];
    const float* g2  = (const float*)d_in[6];
    const float* be2 = (const float*)d_in[7];
    const float* w3  = (const float*)d_in[8];
    const float* g3  = (const float*)d_in[9];
    const float* be3 = (const float*)d_in[10];
    const float* w4  = (const float*)d_in[11];
    const float* b4  = (const float*)d_in[12];
    const float* wb  = (const float*)d_in[13];
    const float* bng = (const float*)d_in[14];
    const float* bnb = (const float*)d_in[15];
    float* out = (float*)d_out;

    const int P_SMEM    = 131072;
    const int MAIN_SMEM = 41552*4;   // 166208
    cudaFuncSetAttribute(p_kernel,    cudaFuncAttributeMaxDynamicSharedMemorySize, P_SMEM);
    cudaFuncSetAttribute(main_kernel, cudaFuncAttributeMaxDynamicSharedMemorySize, MAIN_SMEM);

    prepA_kernel<<<128, 256>>>(wb, bng);
    gather_kernel<<<64*TILES/256, 256>>>(features);
    scores_kernel<<<TILES*KK/256, 256>>>(pts, w1, g1, be1, w2, g2, be2,
                                         w3, g3, be3, w4, b4);
    p_kernel<<<GRID, 256, P_SMEM>>>(wb, bng);
    main_kernel<<<GRID, 256, MAIN_SMEM>>>(features, bnb, out);
}

// round 6
// speedup vs baseline: 5.2023x; 1.7443x over previous
#include <cuda_runtime.h>
#include <cuda_fp16.h>
#include <math.h>
#include <stdint.h>

typedef unsigned long long ull;
typedef unsigned int u32;

#define NP 1024
#define KK 32
#define TILES 8192
#define NPASS 4096
#define GRID 148
#define GRID_MAIN 296

// ---------------- device scratch ----------------
__device__ __align__(16) __half g_Ah[512*72]; // W2' fp16, rows m*64+o, stride 72, cols c
__device__ float g_cen[64*TILES];             // [c][bn]
__device__ float g_scores[TILES*256];         // [tile][k][m]
__device__ float g_P[TILES*512];              // [tile][m*64+o]  (fp32, bn_g-scaled)

#define FMA2(d,a,b)  asm("fma.rn.f32x2 %0, %1, %2, %0;" : "+l"(d) : "l"(a), "l"(b))
#define PACK2(d,x)   asm("mov.b64 %0, {%1, %1};" : "=l"(d) : "f"(x))

__device__ __forceinline__ u32 h2pack(float a, float b) {
    __half2 h = __float22half2_rn(make_float2(a, b));
    return *(u32*)&h;
}
__device__ __forceinline__ void mma16(float* d, u32 a0, u32 a1, u32 a2, u32 a3,
                                      u32 b0, u32 b1) {
    asm volatile(
        "mma.sync.aligned.m16n8k16.row.col.f32.f16.f16.f32 "
        "{%0,%1,%2,%3}, {%4,%5,%6,%7}, {%8,%9}, {%0,%1,%2,%3};"
        : "+f"(d[0]), "+f"(d[1]), "+f"(d[2]), "+f"(d[3])
        : "r"(a0), "r"(a1), "r"(a2), "r"(a3), "r"(b0), "r"(b1));
}

// ---------------- prep: A = fp16(W2'), rows m*64+o ----------------
__global__ void prepA_kernel(const float* __restrict__ wb, const float* __restrict__ bng) {
    int i = blockIdx.x*256 + threadIdx.x;      // i = c*512 + m*64 + o
    int c = i >> 9, row = i & 511;             // row = m*64+o
    float v = (wb[i] + wb[i + 32768]) * bng[i & 63] * rsqrtf(1.f + 1e-5f);
    g_Ah[row*72 + c] = __float2half_rn(v);
}

// ---------------- gather center features ----------------
__global__ void gather_kernel(const float* __restrict__ feat) {
    int i = blockIdx.x*256 + threadIdx.x;      // < 64*8192
    int c = i >> 13; int bn = i & 8191;
    int b = bn >> 10, n = bn & 1023;
    g_cen[i] = feat[((b*64 + c)*NP + n)*KK];   // k = 0
}

// ---------------- score MLP + softmax ----------------
__global__ void scores_kernel(const float* __restrict__ pts,
    const float* __restrict__ w1, const float* __restrict__ g1, const float* __restrict__ be1,
    const float* __restrict__ w2, const float* __restrict__ g2, const float* __restrict__ be2,
    const float* __restrict__ w3, const float* __restrict__ g3, const float* __restrict__ be3,
    const float* __restrict__ w4, const float* __restrict__ b4)
{
    __shared__ float sw1[112], sw2[256], sw3[256], sw4[128];
    __shared__ float sc1[16], sb1[16], sc2[16], sb2[16], sc3[16], sb3[16], sb4[8];
    int t = threadIdx.x;
    float inv = rsqrtf(1.f + 1e-5f);
    if (t < 112) sw1[t] = w1[t];
    if (t < 256) { sw2[t] = w2[t]; sw3[t] = w3[t]; }
    if (t < 128) sw4[t] = w4[t];
    if (t < 16)  { sc1[t] = g1[t]*inv; sb1[t] = be1[t];
                   sc2[t] = g2[t]*inv; sb2[t] = be2[t];
                   sc3[t] = g3[t]*inv; sb3[t] = be3[t]; }
    if (t < 8)   sb4[t] = b4[t];
    __syncthreads();

    int p  = blockIdx.x*256 + t;
    int k  = p & 31;
    int bn = p >> 5;
    int n  = bn & 1023;
    int b  = bn >> 10;

    float xf[7];
    float d2 = 0.f;
#pragma unroll
    for (int d = 0; d < 3; d++) {
        int base = ((b*3 + d)*NP + n)*KK;
        float x  = pts[base + k];
        float cx = pts[base];
        xf[d] = cx;
        float df = x - cx;
        xf[3 + d] = df;
        d2 += df*df;
    }
    xf[6] = sqrtf(d2);

    float h1[16];
#pragma unroll
    for (int i = 0; i < 16; i++) {
        float a = 0.f;
#pragma unroll
        for (int j = 0; j < 7; j++) a += sw1[i*7 + j]*xf[j];
        h1[i] = fmaxf(a*sc1[i] + sb1[i], 0.f);
    }
    float h2[16];
#pragma unroll
    for (int i = 0; i < 16; i++) {
        float a = 0.f;
#pragma unroll
        for (int j = 0; j < 16; j++) a += sw2[i*16 + j]*h1[j];
        h2[i] = fmaxf(a*sc2[i] + sb2[i], 0.f);
    }
    float h3[16];
#pragma unroll
    for (int i = 0; i < 16; i++) {
        float a = 0.f;
#pragma unroll
        for (int j = 0; j < 16; j++) a += sw3[i*16 + j]*h2[j];
        h3[i] = fmaxf(a*sc3[i] + sb3[i], 0.f);
    }
    float s[8];
#pragma unroll
    for (int i = 0; i < 8; i++) {
        float a = sb4[i];
#pragma unroll
        for (int j = 0; j < 16; j++) a += sw4[i*16 + j]*h3[j];
        s[i] = a;
    }
    float mx = s[0];
#pragma unroll
    for (int i = 1; i < 8; i++) mx = fmaxf(mx, s[i]);
    float sum = 0.f;
#pragma unroll
    for (int i = 0; i < 8; i++) { s[i] = __expf(s[i] - mx); sum += s[i]; }
    float r = 1.f / sum;
    float4 v0 = make_float4(s[0]*r, s[1]*r, s[2]*r, s[3]*r);
    float4 v1 = make_float4(s[4]*r, s[5]*r, s[6]*r, s[7]*r);
    ((float4*)(g_scores + p*8))[0] = v0;
    ((float4*)(g_scores + p*8))[1] = v1;
}

// ---------------- P GEMM (fp32 FFMA2, 1024 threads, 16 tiles/batch) ----------------
__global__ void __launch_bounds__(1024, 1)
p_kernel(const float* __restrict__ wb, const float* __restrict__ bng)
{
    extern __shared__ float swb[];   // 32768 floats = 128KB pre-scaled wb_top
    __shared__ ull cen2[16*65];
    int t = threadIdx.x;
    int p = t & 255;                 // mo-pair
    int qt = t >> 8;                 // tile quarter
    float inv = rsqrtf(1.f + 1e-5f);
    for (int i = t; i < 32768; i += 1024) swb[i] = wb[i]*bng[i & 63]*inv;
    __syncthreads();
    for (int batch = blockIdx.x; batch < TILES/16; batch += GRID) {
        int tile0 = batch*16;
        {
            int c = t >> 4, tl = t & 15;
            float v = g_cen[c*8192 + tile0 + tl];
            ull d; PACK2(d, v);
            cen2[tl*65 + c] = d;
        }
        __syncthreads();
        ull acc[4] = {};
#pragma unroll 4
        for (int c = 0; c < 64; c++) {
            ull w2 = *(const ull*)(swb + c*512 + 2*p);
#pragma unroll
            for (int r = 0; r < 4; r++)
                FMA2(acc[r], cen2[(qt*4 + r)*65 + c], w2);
        }
#pragma unroll
        for (int r = 0; r < 4; r++)
            *(ull*)(g_P + (tile0 + qt*4 + r)*512 + 2*p) = acc[r];
        __syncthreads();
    }
}

// ---------------- main: fp16 mma.sync GEMM + fused epilogue (no shfl) ----------------
// smem u32 layout:
//  sAu [0,18432)      A fp16: row (m*64+o) stride 36 half2 (=72 halves)
//  sFu [18432,20736)  B fp16: row c' (0..31) stride 72 half2-cols (2 tiles x 32 k)
//  sS  [20736,21312)  scores fp32 [tl][m*36 + k]
//  sP  [21312,22400)  P fp32 [tl][m*68 + o]
//  sBnb[22400,22464)
__global__ void __launch_bounds__(256, 2)
main_kernel(const float* __restrict__ feat, const float* __restrict__ bnb,
            float* __restrict__ out)
{
    extern __shared__ u32 smu[];
    u32*   sAu  = smu;
    u32*   sFu  = smu + 18432;
    float* sS   = (float*)(smu + 20736);
    float* sP   = (float*)(smu + 21312);
    float* sBnb = (float*)(smu + 22400);

    int t = threadIdx.x;
    int w = t >> 5, lane = t & 31;
    int g = lane >> 2, tid = lane & 3;
    int oc = w & 3;                  // o-chunk of 16
    int khalf = w >> 1 & 0;          // placeholder (recomputed below)
    khalf = w >> 2;                  // 0/1: which 16-k half

    // prologue: copy A (stationary) + bnb
#pragma unroll
    for (int i = 0; i < 18; i++)
        ((float4*)sAu)[t + i*256] = ((const float4*)g_Ah)[t + i*256];
    if (t < 64) sBnb[t] = bnb[t];

    int cnt = (NPASS - 1 - (int)blockIdx.x)/GRID_MAIN + 1;

    float4 rfa[2], rfb[2]; float rs[2]; float rp[4];

    auto stage_ldg = [&](int pp) {
        int tile0 = pp*2; int b = tile0 >> 10; int n0 = tile0 & 1023;
        const float* fbase = feat + ((b*64)*NP + n0)*KK;
#pragma unroll
        for (int j = 0; j < 2; j++) {
            int u = t + j*256;
            int tl = u >> 8, rem = u & 255;
            int cp = rem >> 3, q = rem & 7;
            const float* pa = fbase + (2*cp)*NP*KK + tl*KK + q*4;
            rfa[j] = *(const float4*)pa;
            rfb[j] = *(const float4*)(pa + NP*KK);
        }
#pragma unroll
        for (int j = 0; j < 2; j++) rs[j] = g_scores[tile0*256 + t + j*256];
#pragma unroll
        for (int j = 0; j < 4; j++) rp[j] = g_P[tile0*512 + t + j*256];
    };
    auto stage_sts = [&]() {
#pragma unroll
        for (int j = 0; j < 2; j++) {
            int u = t + j*256;
            int tl = u >> 8, rem = u & 255;
            int cp = rem >> 3, q = rem & 7;
            u32* dst = sFu + cp*72 + tl*KK + q*4;
            float4 fa = rfa[j], fb = rfb[j];
            dst[0] = h2pack(fa.x, fb.x);
            dst[1] = h2pack(fa.y, fb.y);
            dst[2] = h2pack(fa.z, fb.z);
            dst[3] = h2pack(fa.w, fb.w);
        }
#pragma unroll
        for (int j = 0; j < 2; j++) {
            int idx = t + j*256;            // tl*256 + k*8 + m
            int tl = idx >> 8, rem = idx & 255;
            int k = rem >> 3, m = rem & 7;
            sS[tl*288 + m*36 + k] = rs[j];
        }
#pragma unroll
        for (int j = 0; j < 4; j++) {
            int idx = t + j*256;            // tl*512 + m*64 + o
            int tl = idx >> 9, rem = idx & 511;
            int m = rem >> 6, o = rem & 63;
            sP[tl*544 + m*68 + o] = rp[j];
        }
    };

    stage_ldg(blockIdx.x);

    int cp2 = blockIdx.x;
    for (int it = 0; it < cnt; it++, cp2 += GRID_MAIN) {
        stage_sts();
        __syncthreads();
        if (it + 1 < cnt) stage_ldg(cp2 + GRID_MAIN);   // overlaps compute

        int tile0 = cp2*2;
        int b = tile0 >> 10, n0 = tile0 & 1023;
        int o0 = oc*16 + g;

#pragma unroll
        for (int tl = 0; tl < 2; tl++) {
            // B fragments: reused across all 8 m-tiles
            u32 bf[4][2][2];
#pragma unroll
            for (int ks = 0; ks < 4; ks++)
#pragma unroll
                for (int nt = 0; nt < 2; nt++) {
                    int kcol = tl*KK + khalf*16 + nt*8 + g;
                    bf[ks][nt][0] = sFu[(ks*8 + tid)*72 + kcol];
                    bf[ks][nt][1] = sFu[(ks*8 + tid + 4)*72 + kcol];
                }

            float oacc[2][4] = {{0,0,0,0},{0,0,0,0}};
#pragma unroll
            for (int mt = 0; mt < 8; mt++) {
                float acc[2][4] = {{0,0,0,0},{0,0,0,0}};
                int row = mt*64 + o0;
#pragma unroll
                for (int ks = 0; ks < 4; ks++) {
                    const u32* ar = sAu + row*36 + ks*8 + tid;
                    u32 a0 = ar[0];
                    u32 a2 = ar[4];
                    u32 a1 = ar[8*36];
                    u32 a3 = ar[8*36 + 4];
                    mma16(acc[0], a0, a1, a2, a3, bf[ks][0][0], bf[ks][0][1]);
                    mma16(acc[1], a0, a1, a2, a3, bf[ks][1][0], bf[ks][1][1]);
                }
                const float* srow = sS + tl*288 + mt*36 + khalf*16 + tid*2;
                float2 s0 = *(const float2*)(srow);
                float2 s1 = *(const float2*)(srow + 8);
                float p0 = sP[tl*544 + mt*68 + o0];
                float p1 = sP[tl*544 + mt*68 + o0 + 8];
                oacc[0][0] += (acc[0][0] - p0)*s0.x;
                oacc[0][1] += (acc[0][1] - p0)*s0.y;
                oacc[0][2] += (acc[0][2] - p1)*s0.x;
                oacc[0][3] += (acc[0][3] - p1)*s0.y;
                oacc[1][0] += (acc[1][0] - p0)*s1.x;
                oacc[1][1] += (acc[1][1] - p0)*s1.y;
                oacc[1][2] += (acc[1][2] - p1)*s1.x;
                oacc[1][3] += (acc[1][3] - p1)*s1.y;
            }

            int n = n0 + tl;
            float b0 = sBnb[o0], b1 = sBnb[o0 + 8];
            float* ob = out + ((b*64 + o0)*NP + n)*KK + khalf*16 + tid*2;
#pragma unroll
            for (int nt = 0; nt < 2; nt++) {
                float2 r0 = make_float2(fmaxf(oacc[nt][0] + b0, 0.f),
                                        fmaxf(oacc[nt][1] + b0, 0.f));
                float2 r1 = make_float2(fmaxf(oacc[nt][2] + b1, 0.f),
                                        fmaxf(oacc[nt][3] + b1, 0.f));
                *(float2*)(ob + nt*8) = r0;
                *(float2*)(ob + 8*NP*KK + nt*8) = r1;
            }
        }
        __syncthreads();
    }
}

// ---------------- launch ----------------
extern "C" void kernel_launch(void* const* d_in, const int* in_sizes, int n_in,
                              void* d_out, int out_size)
{
    const float* features = (const float*)d_in[0];
    const float* pts      = (const float*)d_in[1];
    const float* w1  = (const float*)d_in[2];
    const float* g1  = (const float*)d_in[3];
    const float* be1 = (const float*)d_in[4];
    const float* w2  = (const float*)d_in[5];
    const float* g2  = (const float*)d_in[6];
    const float* be2 = (const float*)d_in[7];
    const float* w3  = (const float*)d_in[8];
    const float* g3  = (const float*)d_in[9];
    const float* be3 = (const float*)d_in[10];
    const float* w4  = (const float*)d_in[11];
    const float* b4  = (const float*)d_in[12];
    const float* wb  = (const float*)d_in[13];
    const float* bng = (const float*)d_in[14];
    const float* bnb = (const float*)d_in[15];
    float* out = (float*)d_out;

    const int P_SMEM    = 131072;
    const int MAIN_SMEM = 22464*4;   // 89856
    cudaFuncSetAttribute(p_kernel,    cudaFuncAttributeMaxDynamicSharedMemorySize, P_SMEM);
    cudaFuncSetAttribute(main_kernel, cudaFuncAttributeMaxDynamicSharedMemorySize, MAIN_SMEM);

    prepA_kernel<<<128, 256>>>(wb, bng);
    gather_kernel<<<64*TILES/256, 256>>>(features);
    scores_kernel<<<TILES*KK/256, 256>>>(pts, w1, g1, be1, w2, g2, be2,
                                         w3, g3, be3, w4, b4);
    p_kernel<<<GRID, 1024, P_SMEM>>>(wb, bng);
    main_kernel<<<GRID_MAIN, 256, MAIN_SMEM>>>(features, bnb, out);
}

// round 7
// speedup vs baseline: 6.9324x; 1.3326x over previous
#include <cuda_runtime.h>
#include <cuda_fp16.h>
#include <math.h>
#include <stdint.h>

typedef unsigned long long ull;
typedef unsigned int u32;

#define NP 1024
#define KK 32
#define TILES 8192
#define NPASS 4096
#define GRID_P 296
#define GRID_MAIN 296

// ---------------- device scratch ----------------
__device__ __align__(16) __half g_Ah[512*72]; // W2' fp16, rows m*64+o, stride 72, cols c
__device__ float g_scores[TILES*256];         // [tile][k][m]
__device__ float g_P[TILES*512];              // [tile][m*64+o]  (fp32, bn_g-scaled)

__device__ __forceinline__ u32 h2pack(float a, float b) {
    __half2 h = __float22half2_rn(make_float2(a, b));
    return *(u32*)&h;
}
__device__ __forceinline__ void mma16(float* d, u32 a0, u32 a1, u32 a2, u32 a3,
                                      u32 b0, u32 b1) {
    asm volatile(
        "mma.sync.aligned.m16n8k16.row.col.f32.f16.f16.f32 "
        "{%0,%1,%2,%3}, {%4,%5,%6,%7}, {%8,%9}, {%0,%1,%2,%3};"
        : "+f"(d[0]), "+f"(d[1]), "+f"(d[2]), "+f"(d[3])
        : "r"(a0), "r"(a1), "r"(a2), "r"(a3), "r"(b0), "r"(b1));
}

// ---------------- prep: g_Ah = fp16(W2'), rows m*64+o ----------------
__global__ void prepA_kernel(const float* __restrict__ wb, const float* __restrict__ bng) {
    int i = blockIdx.x*256 + threadIdx.x;      // i = c*512 + m*64 + o
    int c = i >> 9, row = i & 511;             // row = m*64+o
    float v = (wb[i] + wb[i + 32768]) * bng[i & 63] * rsqrtf(1.f + 1e-5f);
    g_Ah[row*72 + c] = __float2half_rn(v);
}

// ---------------- score MLP + softmax ----------------
__global__ void scores_kernel(const float* __restrict__ pts,
    const float* __restrict__ w1, const float* __restrict__ g1, const float* __restrict__ be1,
    const float* __restrict__ w2, const float* __restrict__ g2, const float* __restrict__ be2,
    const float* __restrict__ w3, const float* __restrict__ g3, const float* __restrict__ be3,
    const float* __restrict__ w4, const float* __restrict__ b4)
{
    __shared__ float sw1[112], sw2[256], sw3[256], sw4[128];
    __shared__ float sc1[16], sb1[16], sc2[16], sb2[16], sc3[16], sb3[16], sb4[8];
    int t = threadIdx.x;
    float inv = rsqrtf(1.f + 1e-5f);
    if (t < 112) sw1[t] = w1[t];
    if (t < 256) { sw2[t] = w2[t]; sw3[t] = w3[t]; }
    if (t < 128) sw4[t] = w4[t];
    if (t < 16)  { sc1[t] = g1[t]*inv; sb1[t] = be1[t];
                   sc2[t] = g2[t]*inv; sb2[t] = be2[t];
                   sc3[t] = g3[t]*inv; sb3[t] = be3[t]; }
    if (t < 8)   sb4[t] = b4[t];
    __syncthreads();

    int p  = blockIdx.x*256 + t;
    int k  = p & 31;
    int bn = p >> 5;
    int n  = bn & 1023;
    int b  = bn >> 10;

    float xf[7];
    float d2 = 0.f;
#pragma unroll
    for (int d = 0; d < 3; d++) {
        int base = ((b*3 + d)*NP + n)*KK;
        float x  = pts[base + k];
        float cx = pts[base];
        xf[d] = cx;
        float df = x - cx;
        xf[3 + d] = df;
        d2 += df*df;
    }
    xf[6] = sqrtf(d2);

    float h1[16];
#pragma unroll
    for (int i = 0; i < 16; i++) {
        float a = 0.f;
#pragma unroll
        for (int j = 0; j < 7; j++) a += sw1[i*7 + j]*xf[j];
        h1[i] = fmaxf(a*sc1[i] + sb1[i], 0.f);
    }
    float h2[16];
#pragma unroll
    for (int i = 0; i < 16; i++) {
        float a = 0.f;
#pragma unroll
        for (int j = 0; j < 16; j++) a += sw2[i*16 + j]*h1[j];
        h2[i] = fmaxf(a*sc2[i] + sb2[i], 0.f);
    }
    float h3[16];
#pragma unroll
    for (int i = 0; i < 16; i++) {
        float a = 0.f;
#pragma unroll
        for (int j = 0; j < 16; j++) a += sw3[i*16 + j]*h2[j];
        h3[i] = fmaxf(a*sc3[i] + sb3[i], 0.f);
    }
    float s[8];
#pragma unroll
    for (int i = 0; i < 8; i++) {
        float a = sb4[i];
#pragma unroll
        for (int j = 0; j < 16; j++) a += sw4[i*16 + j]*h3[j];
        s[i] = a;
    }
    float mx = s[0];
#pragma unroll
    for (int i = 1; i < 8; i++) mx = fmaxf(mx, s[i]);
    float sum = 0.f;
#pragma unroll
    for (int i = 0; i < 8; i++) { s[i] = __expf(s[i] - mx); sum += s[i]; }
    float r = 1.f / sum;
    float4 v0 = make_float4(s[0]*r, s[1]*r, s[2]*r, s[3]*r);
    float4 v1 = make_float4(s[4]*r, s[5]*r, s[6]*r, s[7]*r);
    ((float4*)(g_scores + p*8))[0] = v0;
    ((float4*)(g_scores + p*8))[1] = v1;
}

// ---------------- P via MMA: P[tile,mo] = sum_c cen[c,tile] * Wtop'[c,mo] ----------------
// smem: sA2 [512 rows mo][36 u32]  (Wtop' fp16, built from wb here)
//       sB  [32 rows cp][24 u32]   (cen fp16 pairs, 16 tile cols)
__global__ void __launch_bounds__(512, 1)
pmma_kernel(const float* __restrict__ feat, const float* __restrict__ wb,
            const float* __restrict__ bng)
{
    extern __shared__ u32 smu[];
    u32* sA2 = smu;                 // 18432 u32
    u32* sB  = smu + 18432;         // 768 u32

    int t = threadIdx.x;
    int w = t >> 5, lane = t & 31;
    int g = lane >> 2, tid = lane & 3;
    float inv = rsqrtf(1.f + 1e-5f);

    // build Wtop' fp16 in smem
    for (int i = t; i < 32768; i += 512) {
        int row = i & 511;                    // m*64+o
        float v = wb[i] * bng[i & 63] * inv;
        ((__half*)sA2)[row*72 + (i >> 9)] = __float2half_rn(v);
    }
    __syncthreads();

    for (int batch = blockIdx.x; batch < TILES/16; batch += GRID_P) {
        int tile0 = batch*16;
        int b = tile0 >> 10, n0 = tile0 & 1023;
        {
            int cp = t >> 4, tl = t & 15;
            const float* fp0 = feat + ((b*64 + 2*cp)*NP + n0 + tl)*KK;
            float va = fp0[0];
            float vb = fp0[NP*KK];
            sB[cp*24 + tl] = h2pack(va, vb);
        }
        __syncthreads();

        u32 bfp[4][2][2];
#pragma unroll
        for (int ks = 0; ks < 4; ks++)
#pragma unroll
            for (int nt = 0; nt < 2; nt++) {
                bfp[ks][nt][0] = sB[(ks*8 + tid)*24 + nt*8 + g];
                bfp[ks][nt][1] = sB[(ks*8 + tid + 4)*24 + nt*8 + g];
            }

#pragma unroll
        for (int it = 0; it < 2; it++) {
            float acc[2][4] = {{0,0,0,0},{0,0,0,0}};
            int row = w*32 + it*16 + g;
#pragma unroll
            for (int ks = 0; ks < 4; ks++) {
                const u32* ar = sA2 + row*36 + ks*8 + tid;
                u32 a0 = ar[0], a2 = ar[4];
                u32 a1 = ar[8*36], a3 = ar[8*36 + 4];
                mma16(acc[0], a0, a1, a2, a3, bfp[ks][0][0], bfp[ks][0][1]);
                mma16(acc[1], a0, a1, a2, a3, bfp[ks][1][0], bfp[ks][1][1]);
            }
#pragma unroll
            for (int nt = 0; nt < 2; nt++) {
                int tcol = tile0 + nt*8 + 2*tid;
                g_P[tcol*512 + row]           = acc[nt][0];
                g_P[(tcol + 1)*512 + row]     = acc[nt][1];
                g_P[tcol*512 + row + 8]       = acc[nt][2];
                g_P[(tcol + 1)*512 + row + 8] = acc[nt][3];
            }
        }
        __syncthreads();
    }
}

// ---------------- main: fp16 mma.sync GEMM + fused epilogue ----------------
// smem u32 layout:
//  sAu [0,18432)      A fp16: row (m*64+o) stride 36 u32 (=72 halves)
//  sFu [18432,20736)  B fp16: row cp (0..31) stride 72 u32 (2 tiles x 32 k)
//  sS  [20736,21312)  scores fp32 [tl][m*36 + k]
//  sP  [21312,22400)  P fp32 [tl][m*68 + o]
//  sBnb[22400,22464)
__global__ void __launch_bounds__(256, 2)
main_kernel(const float* __restrict__ feat, const float* __restrict__ bnb,
            float* __restrict__ out)
{
    extern __shared__ u32 smu[];
    u32*   sAu  = smu;
    u32*   sFu  = smu + 18432;
    float* sS   = (float*)(smu + 20736);
    float* sP   = (float*)(smu + 21312);
    float* sBnb = (float*)(smu + 22400);

    int t = threadIdx.x;
    int w = t >> 5, lane = t & 31;
    int g = lane >> 2, tid = lane & 3;
    int oc = w & 3;                  // o-chunk of 16
    int khalf = w >> 2;              // which 16-k half

    // prologue: copy A (stationary) + bnb
#pragma unroll
    for (int i = 0; i < 18; i++)
        ((float4*)sAu)[t + i*256] = ((const float4*)g_Ah)[t + i*256];
    if (t < 64) sBnb[t] = bnb[t];

    int cnt = (NPASS - 1 - (int)blockIdx.x)/GRID_MAIN + 1;

    float4 rfa[2], rfb[2]; float rs[2]; float rp[4];

    auto stage_ldg = [&](int pp) {
        int tile0 = pp*2; int b = tile0 >> 10; int n0 = tile0 & 1023;
        const float* fbase = feat + ((b*64)*NP + n0)*KK;
#pragma unroll
        for (int j = 0; j < 2; j++) {
            int u = t + j*256;
            int tl = u >> 8, rem = u & 255;
            int cp = rem >> 3, q = rem & 7;
            const float* pa = fbase + (2*cp)*NP*KK + tl*KK + q*4;
            rfa[j] = *(const float4*)pa;
            rfb[j] = *(const float4*)(pa + NP*KK);
        }
#pragma unroll
        for (int j = 0; j < 2; j++) rs[j] = g_scores[tile0*256 + t + j*256];
#pragma unroll
        for (int j = 0; j < 4; j++) rp[j] = g_P[tile0*512 + t + j*256];
    };
    auto stage_sts = [&]() {
#pragma unroll
        for (int j = 0; j < 2; j++) {
            int u = t + j*256;
            int tl = u >> 8, rem = u & 255;
            int cp = rem >> 3, q = rem & 7;
            u32* dst = sFu + cp*72 + tl*KK + q*4;
            float4 fa = rfa[j], fb = rfb[j];
            dst[0] = h2pack(fa.x, fb.x);
            dst[1] = h2pack(fa.y, fb.y);
            dst[2] = h2pack(fa.z, fb.z);
            dst[3] = h2pack(fa.w, fb.w);
        }
#pragma unroll
        for (int j = 0; j < 2; j++) {
            int idx = t + j*256;            // tl*256 + k*8 + m
            int tl = idx >> 8, rem = idx & 255;
            int k = rem >> 3, m = rem & 7;
            sS[tl*288 + m*36 + k] = rs[j];
        }
#pragma unroll
        for (int j = 0; j < 4; j++) {
            int idx = t + j*256;            // tl*512 + m*64 + o
            int tl = idx >> 9, rem = idx & 511;
            int m = rem >> 6, o = rem & 63;
            sP[tl*544 + m*68 + o] = rp[j];
        }
    };

    stage_ldg(blockIdx.x);

    int cp2 = blockIdx.x;
    for (int it = 0; it < cnt; it++, cp2 += GRID_MAIN) {
        stage_sts();
        __syncthreads();
        if (it + 1 < cnt) stage_ldg(cp2 + GRID_MAIN);   // overlaps compute

        int tile0 = cp2*2;
        int b = tile0 >> 10, n0 = tile0 & 1023;
        int o0 = oc*16 + g;

        // all B fragments for this pass (both tiles, both n-blocks)
        u32 bf[4][2][2][2];   // [ks][tl][nt][2]
#pragma unroll
        for (int ks = 0; ks < 4; ks++)
#pragma unroll
            for (int tl = 0; tl < 2; tl++)
#pragma unroll
                for (int nt = 0; nt < 2; nt++) {
                    int kcol = tl*KK + khalf*16 + nt*8 + g;
                    bf[ks][tl][nt][0] = sFu[(ks*8 + tid)*72 + kcol];
                    bf[ks][tl][nt][1] = sFu[(ks*8 + tid + 4)*72 + kcol];
                }

        float oacc[2][2][4];
#pragma unroll
        for (int tl = 0; tl < 2; tl++)
#pragma unroll
            for (int nt = 0; nt < 2; nt++)
#pragma unroll
                for (int r = 0; r < 4; r++) oacc[tl][nt][r] = 0.f;

#pragma unroll
        for (int mt = 0; mt < 8; mt++) {
            float acc[2][2][4];
#pragma unroll
            for (int tl = 0; tl < 2; tl++)
#pragma unroll
                for (int nt = 0; nt < 2; nt++)
#pragma unroll
                    for (int r = 0; r < 4; r++) acc[tl][nt][r] = 0.f;

            int row = mt*64 + o0;
#pragma unroll
            for (int ks = 0; ks < 4; ks++) {
                const u32* ar = sAu + row*36 + ks*8 + tid;
                u32 a0 = ar[0], a2 = ar[4];
                u32 a1 = ar[8*36], a3 = ar[8*36 + 4];
                mma16(acc[0][0], a0, a1, a2, a3, bf[ks][0][0][0], bf[ks][0][0][1]);
                mma16(acc[0][1], a0, a1, a2, a3, bf[ks][0][1][0], bf[ks][0][1][1]);
                mma16(acc[1][0], a0, a1, a2, a3, bf[ks][1][0][0], bf[ks][1][0][1]);
                mma16(acc[1][1], a0, a1, a2, a3, bf[ks][1][1][0], bf[ks][1][1][1]);
            }
#pragma unroll
            for (int tl = 0; tl < 2; tl++) {
                const float* srow = sS + tl*288 + mt*36 + khalf*16 + tid*2;
                float2 s0 = *(const float2*)(srow);
                float2 s1 = *(const float2*)(srow + 8);
                float p0 = sP[tl*544 + mt*68 + o0];
                float p1 = sP[tl*544 + mt*68 + o0 + 8];
                oacc[tl][0][0] += (acc[tl][0][0] - p0)*s0.x;
                oacc[tl][0][1] += (acc[tl][0][1] - p0)*s0.y;
                oacc[tl][0][2] += (acc[tl][0][2] - p1)*s0.x;
                oacc[tl][0][3] += (acc[tl][0][3] - p1)*s0.y;
                oacc[tl][1][0] += (acc[tl][1][0] - p0)*s1.x;
                oacc[tl][1][1] += (acc[tl][1][1] - p0)*s1.y;
                oacc[tl][1][2] += (acc[tl][1][2] - p1)*s1.x;
                oacc[tl][1][3] += (acc[tl][1][3] - p1)*s1.y;
            }
        }

        float b0 = sBnb[o0], b1 = sBnb[o0 + 8];
#pragma unroll
        for (int tl = 0; tl < 2; tl++) {
            int n = n0 + tl;
            float* ob = out + ((b*64 + o0)*NP + n)*KK + khalf*16 + tid*2;
#pragma unroll
            for (int nt = 0; nt < 2; nt++) {
                float2 r0 = make_float2(fmaxf(oacc[tl][nt][0] + b0, 0.f),
                                        fmaxf(oacc[tl][nt][1] + b0, 0.f));
                float2 r1 = make_float2(fmaxf(oacc[tl][nt][2] + b1, 0.f),
                                        fmaxf(oacc[tl][nt][3] + b1, 0.f));
                *(float2*)(ob + nt*8) = r0;
                *(float2*)(ob + 8*NP*KK + nt*8) = r1;
            }
        }
        __syncthreads();
    }
}

// ---------------- launch ----------------
extern "C" void kernel_launch(void* const* d_in, const int* in_sizes, int n_in,
                              void* d_out, int out_size)
{
    const float* features = (const float*)d_in[0];
    const float* pts      = (const float*)d_in[1];
    const float* w1  = (const float*)d_in[2];
    const float* g1  = (const float*)d_in[3];
    const float* be1 = (const float*)d_in[4];
    const float* w2  = (const float*)d_in[5];
    const float* g2  = (const float*)d_in[6];
    const float* be2 = (const float*)d_in[7];
    const float* w3  = (const float*)d_in[8];
    const float* g3  = (const float*)d_in[9];
    const float* be3 = (const float*)d_in[10];
    const float* w4  = (const float*)d_in[11];
    const float* b4  = (const float*)d_in[12];
    const float* wb  = (const float*)d_in[13];
    const float* bng = (const float*)d_in[14];
    const float* bnb = (const float*)d_in[15];
    float* out = (float*)d_out;

    const int PMMA_SMEM = (18432 + 768)*4;   // 76800
    const int MAIN_SMEM = 22464*4;           // 89856
    cudaFuncSetAttribute(pmma_kernel, cudaFuncAttributeMaxDynamicSharedMemorySize, PMMA_SMEM);
    cudaFuncSetAttribute(main_kernel, cudaFuncAttributeMaxDynamicSharedMemorySize, MAIN_SMEM);

    prepA_kernel<<<128, 256>>>(wb, bng);
    scores_kernel<<<TILES*KK/256, 256>>>(pts, w1, g1, be1, w2, g2, be2,
                                         w3, g3, be3, w4, b4);
    pmma_kernel<<<GRID_P, 512, PMMA_SMEM>>>(features, wb, bng);
    main_kernel<<<GRID_MAIN, 256, MAIN_SMEM>>>(features, bnb, out);
}

// round 8
// speedup vs baseline: 7.1436x; 1.0305x over previous
#include <cuda_runtime.h>
#include <cuda_fp16.h>
#include <math.h>
#include <stdint.h>

typedef unsigned long long ull;
typedef unsigned int u32;

#define NP 1024
#define KK 32
#define TILES 8192
#define NPASS 4096
#define GRID_P 296
#define GRID_MAIN 296
#define PRE_GRID 872   // 296 pmma + 512 scores + 64 prepA

// ---------------- device scratch ----------------
__device__ __align__(16) __half g_Ah[512*72]; // W2' fp16, rows m*64+o, stride 72, cols c
__device__ float g_scores[TILES*256];         // [tile][k][m]
__device__ float g_P[TILES*512];              // [tile][m*64+o]  (fp32, bn_g-scaled)

__device__ __forceinline__ u32 h2pack(float a, float b) {
    __half2 h = __float22half2_rn(make_float2(a, b));
    return *(u32*)&h;
}
__device__ __forceinline__ void mma16(float* d, u32 a0, u32 a1, u32 a2, u32 a3,
                                      u32 b0, u32 b1) {
    asm volatile(
        "mma.sync.aligned.m16n8k16.row.col.f32.f16.f16.f32 "
        "{%0,%1,%2,%3}, {%4,%5,%6,%7}, {%8,%9}, {%0,%1,%2,%3};"
        : "+f"(d[0]), "+f"(d[1]), "+f"(d[2]), "+f"(d[3])
        : "r"(a0), "r"(a1), "r"(a2), "r"(a3), "r"(b0), "r"(b1));
}
#define LDSM4(r0,r1,r2,r3,addr) \
    asm volatile("ldmatrix.sync.aligned.m8n8.x4.shared.b16 {%0,%1,%2,%3}, [%4];" \
        : "=r"(r0), "=r"(r1), "=r"(r2), "=r"(r3) : "r"(addr))

// =================== fused pre kernel ===================
// blocks [0,296)    : pmma  — P[tile,mo] = sum_c cen[c,tile]*Wtop'[c,mo]
// blocks [296,808)  : scores MLP+softmax (512 pts/block)
// blocks [808,872)  : prepA — g_Ah = fp16(W2'), rows m*64+o
__global__ void __launch_bounds__(512, 2)
pre_kernel(const float* __restrict__ feat, const float* __restrict__ pts,
    const float* __restrict__ w1, const float* __restrict__ g1, const float* __restrict__ be1,
    const float* __restrict__ w2, const float* __restrict__ g2, const float* __restrict__ be2,
    const float* __restrict__ w3, const float* __restrict__ g3, const float* __restrict__ be3,
    const float* __restrict__ w4, const float* __restrict__ b4,
    const float* __restrict__ wb, const float* __restrict__ bng)
{
    int bid = blockIdx.x;
    int t = threadIdx.x;
    float inv = rsqrtf(1.f + 1e-5f);

    if (bid >= 808) {       // ---- prepA ----
        int i = (bid - 808)*512 + t;           // i = c*512 + m*64 + o
        int c = i >> 9, row = i & 511;
        float v = (wb[i] + wb[i + 32768]) * bng[i & 63] * inv;
        g_Ah[row*72 + c] = __float2half_rn(v);
        return;
    }

    if (bid >= 296) {       // ---- scores ----
        __shared__ float sw1[112], sw2[256], sw3[256], sw4[128];
        __shared__ float sc1[16], sb1[16], sc2[16], sb2[16], sc3[16], sb3[16], sb4[8];
        if (t < 112) sw1[t] = w1[t];
        if (t < 256) { sw2[t] = w2[t]; sw3[t] = w3[t]; }
        if (t < 128) sw4[t] = w4[t];
        if (t < 16)  { sc1[t] = g1[t]*inv; sb1[t] = be1[t];
                       sc2[t] = g2[t]*inv; sb2[t] = be2[t];
                       sc3[t] = g3[t]*inv; sb3[t] = be3[t]; }
        if (t < 8)   sb4[t] = b4[t];
        __syncthreads();

        int p  = (bid - 296)*512 + t;
        int k  = p & 31;
        int bn = p >> 5;
        int n  = bn & 1023;
        int b  = bn >> 10;

        float xf[7];
        float d2 = 0.f;
#pragma unroll
        for (int d = 0; d < 3; d++) {
            int base = ((b*3 + d)*NP + n)*KK;
            float x  = pts[base + k];
            float cx = pts[base];
            xf[d] = cx;
            float df = x - cx;
            xf[3 + d] = df;
            d2 += df*df;
        }
        xf[6] = sqrtf(d2);

        float h1[16];
#pragma unroll
        for (int i = 0; i < 16; i++) {
            float a = 0.f;
#pragma unroll
            for (int j = 0; j < 7; j++) a += sw1[i*7 + j]*xf[j];
            h1[i] = fmaxf(a*sc1[i] + sb1[i], 0.f);
        }
        float h2[16];
#pragma unroll
        for (int i = 0; i < 16; i++) {
            float a = 0.f;
#pragma unroll
            for (int j = 0; j < 16; j++) a += sw2[i*16 + j]*h1[j];
            h2[i] = fmaxf(a*sc2[i] + sb2[i], 0.f);
        }
        float h3[16];
#pragma unroll
        for (int i = 0; i < 16; i++) {
            float a = 0.f;
#pragma unroll
            for (int j = 0; j < 16; j++) a += sw3[i*16 + j]*h2[j];
            h3[i] = fmaxf(a*sc3[i] + sb3[i], 0.f);
        }
        float s[8];
#pragma unroll
        for (int i = 0; i < 8; i++) {
            float a = sb4[i];
#pragma unroll
            for (int j = 0; j < 16; j++) a += sw4[i*16 + j]*h3[j];
            s[i] = a;
        }
        float mx = s[0];
#pragma unroll
        for (int i = 1; i < 8; i++) mx = fmaxf(mx, s[i]);
        float sum = 0.f;
#pragma unroll
        for (int i = 0; i < 8; i++) { s[i] = __expf(s[i] - mx); sum += s[i]; }
        float r = 1.f / sum;
        float4 v0 = make_float4(s[0]*r, s[1]*r, s[2]*r, s[3]*r);
        float4 v1 = make_float4(s[4]*r, s[5]*r, s[6]*r, s[7]*r);
        ((float4*)(g_scores + p*8))[0] = v0;
        ((float4*)(g_scores + p*8))[1] = v1;
        return;
    }

    // ---- pmma ----
    extern __shared__ u32 smu[];
    u32* sA2 = smu;                 // 18432 u32
    u32* sB  = smu + 18432;         // 768 u32

    int w = t >> 5, lane = t & 31;
    int g = lane >> 2, tid = lane & 3;

    for (int i = t; i < 32768; i += 512) {
        int row = i & 511;                    // m*64+o
        float v = wb[i] * bng[i & 63] * inv;
        ((__half*)sA2)[row*72 + (i >> 9)] = __float2half_rn(v);
    }
    __syncthreads();

    for (int batch = bid; batch < TILES/16; batch += GRID_P) {
        int tile0 = batch*16;
        int b = tile0 >> 10, n0 = tile0 & 1023;
        {
            int cp = t >> 4, tl = t & 15;
            const float* fp0 = feat + ((b*64 + 2*cp)*NP + n0 + tl)*KK;
            float va = fp0[0];
            float vb = fp0[NP*KK];
            sB[cp*24 + tl] = h2pack(va, vb);
        }
        __syncthreads();

        u32 bfp[4][2][2];
#pragma unroll
        for (int ks = 0; ks < 4; ks++)
#pragma unroll
            for (int nt = 0; nt < 2; nt++) {
                bfp[ks][nt][0] = sB[(ks*8 + tid)*24 + nt*8 + g];
                bfp[ks][nt][1] = sB[(ks*8 + tid + 4)*24 + nt*8 + g];
            }

#pragma unroll
        for (int it = 0; it < 2; it++) {
            float acc[2][4] = {{0,0,0,0},{0,0,0,0}};
            int row = w*32 + it*16 + g;
#pragma unroll
            for (int ks = 0; ks < 4; ks++) {
                const u32* ar = sA2 + row*36 + ks*8 + tid;
                u32 a0 = ar[0], a2 = ar[4];
                u32 a1 = ar[8*36], a3 = ar[8*36 + 4];
                mma16(acc[0], a0, a1, a2, a3, bfp[ks][0][0], bfp[ks][0][1]);
                mma16(acc[1], a0, a1, a2, a3, bfp[ks][1][0], bfp[ks][1][1]);
            }
#pragma unroll
            for (int nt = 0; nt < 2; nt++) {
                int tcol = tile0 + nt*8 + 2*tid;
                g_P[tcol*512 + row]           = acc[nt][0];
                g_P[(tcol + 1)*512 + row]     = acc[nt][1];
                g_P[tcol*512 + row + 8]       = acc[nt][2];
                g_P[(tcol + 1)*512 + row + 8] = acc[nt][3];
            }
        }
        __syncthreads();
    }
}

// ---------------- main: fp16 mma.sync GEMM (ldmatrix A) + fused epilogue ----------------
// smem u32 layout:
//  sAu [0,18432)      A fp16: row (m*64+o) stride 36 u32 (=72 halves)
//  sFu [18432,20736)  B fp16: row cp (0..31) stride 72 u32 (2 tiles x 32 k)
//  sS  [20736,21312)  scores fp32 [tl][m*36 + k]
//  sP  [21312,22400)  P fp32 [tl][m*68 + o]
//  sBnb[22400,22464)
__global__ void __launch_bounds__(256, 2)
main_kernel(const float* __restrict__ feat, const float* __restrict__ bnb,
            float* __restrict__ out)
{
    extern __shared__ u32 smu[];
    u32*   sAu  = smu;
    u32*   sFu  = smu + 18432;
    float* sS   = (float*)(smu + 20736);
    float* sP   = (float*)(smu + 21312);
    float* sBnb = (float*)(smu + 22400);

    int t = threadIdx.x;
    int w = t >> 5, lane = t & 31;
    int g = lane >> 2, tid = lane & 3;
    int oc = w & 3;                  // o-chunk of 16
    int khalf = w >> 2;              // which 16-k half

    // ldmatrix per-lane base address (bytes): row = oc*16 + rowoff, + k-half select
    int rowoff = ((lane >> 3) & 1)*8 + (lane & 7);
    int kbyte  = (lane >> 4)*16;
    u32 abase = (u32)__cvta_generic_to_shared(sAu) + (u32)(oc*16 + rowoff)*144u + (u32)kbyte;

    // prologue: copy A (stationary) + bnb
#pragma unroll
    for (int i = 0; i < 18; i++)
        ((float4*)sAu)[t + i*256] = ((const float4*)g_Ah)[t + i*256];
    if (t < 64) sBnb[t] = bnb[t];

    int cnt = (NPASS - 1 - (int)blockIdx.x)/GRID_MAIN + 1;

    float4 rfa[2], rfb[2]; float rs[2]; float rp[4];

    auto stage_ldg = [&](int pp) {
        int tile0 = pp*2; int b = tile0 >> 10; int n0 = tile0 & 1023;
        const float* fbase = feat + ((b*64)*NP + n0)*KK;
#pragma unroll
        for (int j = 0; j < 2; j++) {
            int u = t + j*256;
            int tl = u >> 8, rem = u & 255;
            int cp = rem >> 3, q = rem & 7;
            const float* pa = fbase + (2*cp)*NP*KK + tl*KK + q*4;
            rfa[j] = *(const float4*)pa;
            rfb[j] = *(const float4*)(pa + NP*KK);
        }
#pragma unroll
        for (int j = 0; j < 2; j++) rs[j] = g_scores[tile0*256 + t + j*256];
#pragma unroll
        for (int j = 0; j < 4; j++) rp[j] = g_P[tile0*512 + t + j*256];
    };
    auto stage_sts = [&]() {
#pragma unroll
        for (int j = 0; j < 2; j++) {
            int u = t + j*256;
            int tl = u >> 8, rem = u & 255;
            int cp = rem >> 3, q = rem & 7;
            u32* dst = sFu + cp*72 + tl*KK + q*4;
            float4 fa = rfa[j], fb = rfb[j];
            dst[0] = h2pack(fa.x, fb.x);
            dst[1] = h2pack(fa.y, fb.y);
            dst[2] = h2pack(fa.z, fb.z);
            dst[3] = h2pack(fa.w, fb.w);
        }
#pragma unroll
        for (int j = 0; j < 2; j++) {
            int idx = t + j*256;            // tl*256 + k*8 + m
            int tl = idx >> 8, rem = idx & 255;
            int k = rem >> 3, m = rem & 7;
            sS[tl*288 + m*36 + k] = rs[j];
        }
#pragma unroll
        for (int j = 0; j < 4; j++) {
            int idx = t + j*256;            // tl*512 + m*64 + o
            int tl = idx >> 9, rem = idx & 511;
            int m = rem >> 6, o = rem & 63;
            sP[tl*544 + m*68 + o] = rp[j];
        }
    };

    stage_ldg(blockIdx.x);

    int cp2 = blockIdx.x;
    for (int it = 0; it < cnt; it++, cp2 += GRID_MAIN) {
        stage_sts();
        __syncthreads();
        if (it + 1 < cnt) stage_ldg(cp2 + GRID_MAIN);   // overlaps compute

        int tile0 = cp2*2;
        int b = tile0 >> 10, n0 = tile0 & 1023;
        int o0 = oc*16 + g;

        // all B fragments for this pass (both tiles, both n-blocks)
        u32 bf[4][2][2][2];   // [ks][tl][nt][2]
#pragma unroll
        for (int ks = 0; ks < 4; ks++)
#pragma unroll
            for (int tl = 0; tl < 2; tl++)
#pragma unroll
                for (int nt = 0; nt < 2; nt++) {
                    int kcol = tl*KK + khalf*16 + nt*8 + g;
                    bf[ks][tl][nt][0] = sFu[(ks*8 + tid)*72 + kcol];
                    bf[ks][tl][nt][1] = sFu[(ks*8 + tid + 4)*72 + kcol];
                }

        float oacc[2][2][4];
#pragma unroll
        for (int tl = 0; tl < 2; tl++)
#pragma unroll
            for (int nt = 0; nt < 2; nt++)
#pragma unroll
                for (int r = 0; r < 4; r++) oacc[tl][nt][r] = 0.f;

#pragma unroll
        for (int mt = 0; mt < 8; mt++) {
            float acc[2][2][4];
#pragma unroll
            for (int tl = 0; tl < 2; tl++)
#pragma unroll
                for (int nt = 0; nt < 2; nt++)
#pragma unroll
                    for (int r = 0; r < 4; r++) acc[tl][nt][r] = 0.f;

            u32 amt = abase + (u32)mt*9216u;
#pragma unroll
            for (int ks = 0; ks < 4; ks++) {
                u32 a0, a1, a2, a3;
                LDSM4(a0, a1, a2, a3, amt + (u32)ks*32u);
                mma16(acc[0][0], a0, a1, a2, a3, bf[ks][0][0][0], bf[ks][0][0][1]);
                mma16(acc[0][1], a0, a1, a2, a3, bf[ks][0][1][0], bf[ks][0][1][1]);
                mma16(acc[1][0], a0, a1, a2, a3, bf[ks][1][0][0], bf[ks][1][0][1]);
                mma16(acc[1][1], a0, a1, a2, a3, bf[ks][1][1][0], bf[ks][1][1][1]);
            }
#pragma unroll
            for (int tl = 0; tl < 2; tl++) {
                const float* srow = sS + tl*288 + mt*36 + khalf*16 + tid*2;
                float2 s0 = *(const float2*)(srow);
                float2 s1 = *(const float2*)(srow + 8);
                float p0 = sP[tl*544 + mt*68 + o0];
                float p1 = sP[tl*544 + mt*68 + o0 + 8];
                oacc[tl][0][0] += (acc[tl][0][0] - p0)*s0.x;
                oacc[tl][0][1] += (acc[tl][0][1] - p0)*s0.y;
                oacc[tl][0][2] += (acc[tl][0][2] - p1)*s0.x;
                oacc[tl][0][3] += (acc[tl][0][3] - p1)*s0.y;
                oacc[tl][1][0] += (acc[tl][1][0] - p0)*s1.x;
                oacc[tl][1][1] += (acc[tl][1][1] - p0)*s1.y;
                oacc[tl][1][2] += (acc[tl][1][2] - p1)*s1.x;
                oacc[tl][1][3] += (acc[tl][1][3] - p1)*s1.y;
            }
        }

        float b0 = sBnb[o0], b1 = sBnb[o0 + 8];
#pragma unroll
        for (int tl = 0; tl < 2; tl++) {
            int n = n0 + tl;
            float* ob = out + ((b*64 + o0)*NP + n)*KK + khalf*16 + tid*2;
#pragma unroll
            for (int nt = 0; nt < 2; nt++) {
                float2 r0 = make_float2(fmaxf(oacc[tl][nt][0] + b0, 0.f),
                                        fmaxf(oacc[tl][nt][1] + b0, 0.f));
                float2 r1 = make_float2(fmaxf(oacc[tl][nt][2] + b1, 0.f),
                                        fmaxf(oacc[tl][nt][3] + b1, 0.f));
                *(float2*)(ob + nt*8) = r0;
                *(float2*)(ob + 8*NP*KK + nt*8) = r1;
            }
        }
        __syncthreads();
    }
}

// ---------------- launch ----------------
extern "C" void kernel_launch(void* const* d_in, const int* in_sizes, int n_in,
                              void* d_out, int out_size)
{
    const float* features = (const float*)d_in[0];
    const float* pts      = (const float*)d_in[1];
    const float* w1  = (const float*)d_in[2];
    const float* g1  = (const float*)d_in[3];
    const float* be1 = (const float*)d_in[4];
    const float* w2  = (const float*)d_in[5];
    const float* g2  = (const float*)d_in[6];
    const float* be2 = (const float*)d_in[7];
    const float* w3  = (const float*)d_in[8];
    const float* g3  = (const float*)d_in[9];
    const float* be3 = (const float*)d_in[10];
    const float* w4  = (const float*)d_in[11];
    const float* b4  = (const float*)d_in[12];
    const float* wb  = (const float*)d_in[13];
    const float* bng = (const float*)d_in[14];
    const float* bnb = (const float*)d_in[15];
    float* out = (float*)d_out;

    const int PRE_SMEM  = (18432 + 768)*4;   // 76800
    const int MAIN_SMEM = 22464*4;           // 89856
    cudaFuncSetAttribute(pre_kernel,  cudaFuncAttributeMaxDynamicSharedMemorySize, PRE_SMEM);
    cudaFuncSetAttribute(main_kernel, cudaFuncAttributeMaxDynamicSharedMemorySize, MAIN_SMEM);

    pre_kernel<<<PRE_GRID, 512, PRE_SMEM>>>(features, pts,
        w1, g1, be1, w2, g2, be2, w3, g3, be3, w4, b4, wb, bng);
    main_kernel<<<GRID_MAIN, 256, MAIN_SMEM>>>(features, bnb, out);
}